// round 13
// baseline (speedup 1.0000x reference)
#include <cuda_runtime.h>
#include <cuda_fp16.h>
#include <math.h>

#define HID   1024
#define G4    4096
#define NB    32
#define NT    100
#define IND   132
#define OUTW  13200
#define NBLK  129
#define NTHR  288

// K=128 stage tiles (bytes); plane-major s8: [2][rows][144]
#define TILE_W  36864   // 2 x 128 x 144
#define TILE_A  9216    // 2 x 32 x 144
#define SLOT    46080
#define OF_A    36864
#define DEPTH   4
#define CTRL    184320  // 4*SLOT
#define SMEM_ALL 184448
#define TXB     46080
#define PLW     18432   // plane offset within W tile (128*144)
#define PLA     4608    // plane offset within A tile (32*144)

// ---------------- persistent device scratch (pre-tiled, s8 dual-plane) ----------------
// matrices: 0 Whh1(L0), 1 Wih2(L1), 2 Whh2(L1), 3 Wih3(L2), 4 Whh3(L2), 5 Mw(L0)
__device__ unsigned char g_WQ[6][32][8][2][128][144];
__device__ unsigned char g_W1Q[32][2][2][128][144];   // Wih1, K padded to 256 (2 kb)
__device__ unsigned char g_xQ[NT][2][2][32][144];     // frames quantized, tiled
__device__ unsigned char g_hQ[2][3][8][2][32][144];   // h quantized, tiled per kb
__device__ float         g_hf[2][3][NB][HID];         // fp32 h for decoder
__device__ float         g_c[3][NB][HID];
__device__ float         g_bs[3][G4];
__device__ float         g_bsM[G4];
__device__ unsigned      g_bar;

// ---------------- asm helpers ----------------
__device__ __forceinline__ unsigned sptr(const void* p) {
    return (unsigned)__cvta_generic_to_shared(p);
}
__device__ __forceinline__ void bulkcp(unsigned dst, const void* src, unsigned bytes,
                                       unsigned mbar) {
    asm volatile(
        "cp.async.bulk.shared::cluster.global.mbarrier::complete_tx::bytes "
        "[%0], [%1], %2, [%3];"
        :: "r"(dst), "l"(src), "r"(bytes), "r"(mbar) : "memory");
}
__device__ __forceinline__ void mbar_init(unsigned a, unsigned cnt) {
    asm volatile("mbarrier.init.shared.b64 [%0], %1;" :: "r"(a), "r"(cnt) : "memory");
}
__device__ __forceinline__ void mbar_expect(unsigned a, unsigned tx) {
    asm volatile("mbarrier.arrive.expect_tx.shared.b64 _, [%0], %1;"
                 :: "r"(a), "r"(tx) : "memory");
}
__device__ __forceinline__ void mbar_arrive(unsigned a) {
    asm volatile("mbarrier.arrive.shared.b64 _, [%0];" :: "r"(a) : "memory");
}
__device__ __forceinline__ void mbar_wait(unsigned a, unsigned par) {
    asm volatile(
        "{\n\t.reg .pred P;\n\t"
        "W_%=:\n\t"
        "mbarrier.try_wait.parity.acquire.cta.shared::cta.b64 P, [%0], %1, 0x989680;\n\t"
        "@P bra.uni D_%=;\n\t"
        "bra.uni W_%=;\n\t"
        "D_%=:\n\t}"
        :: "r"(a), "r"(par) : "memory");
}
__device__ __forceinline__ void fence_async() {
    asm volatile("fence.proxy.async.shared::cta;" ::: "memory");
}
__device__ __forceinline__ void ldmX4(unsigned a[4], unsigned addr) {
    asm volatile("ldmatrix.sync.aligned.m8n8.x4.shared.b16 {%0,%1,%2,%3}, [%4];"
                 : "=r"(a[0]), "=r"(a[1]), "=r"(a[2]), "=r"(a[3]) : "r"(addr));
}
__device__ __forceinline__ void imma(int c[4], const unsigned a[4],
                                     unsigned b0, unsigned b1) {
    asm volatile("mma.sync.aligned.m16n8k32.row.col.s32.s8.s8.s32 "
                 "{%0,%1,%2,%3}, {%4,%5,%6,%7}, {%8,%9}, {%0,%1,%2,%3};"
                 : "+r"(c[0]), "+r"(c[1]), "+r"(c[2]), "+r"(c[3])
                 : "r"(a[0]), "r"(a[1]), "r"(a[2]), "r"(a[3]), "r"(b0), "r"(b1));
}
__device__ __forceinline__ float sigm(float x) { return 1.0f / (1.0f + __expf(-x)); }
__device__ __forceinline__ int growf(int n, int j0) { return ((n >> 5) << 10) + j0 + (n & 31); }

// quantize to two s8 planes
__device__ __forceinline__ void q2p(float v, float scale, signed char* hi, signed char* lo) {
    int q = __float2int_rn(v * scale);
    q = max(-32767, min(32767, q));
    int q1 = (q + 128) >> 8;
    *hi = (signed char)q1;
    *lo = (signed char)(q - (q1 << 8));
}

// ---------------- grid barrier ----------------
__device__ __forceinline__ void gridbar() {
    __syncthreads();
    if (threadIdx.x == 0) {
        __threadfence();
        unsigned gen = atomicAdd(&g_bar, 1u);
        unsigned target = gen - (gen % NBLK) + NBLK;
        while (*(volatile unsigned*)&g_bar < target) { }
        __threadfence();
    }
    __syncthreads();
}

// ---------------- decoder core ----------------
__device__ void dec_core(float* smf, int db, int tid,
                         const float* __restrict__ h2, const float* __restrict__ wdec,
                         const float* __restrict__ bdec, float* __restrict__ outp, int toff)
{
    float* sh2 = smf;
    float* sWd = smf + 32 * 257;
    const int o0 = db * 4;
    const int oo = tid & 3, b = (tid >> 2) & 31;
    float acc = 0.0f;
    for (int k0 = 0; k0 < HID; k0 += 256) {
        __syncthreads();
        for (int li = tid; li < 8192; li += NTHR) {
            int r = li >> 8, c = li & 255;
            sh2[r * 257 + c] = h2[r * HID + k0 + c];
        }
        for (int li = tid; li < 1024; li += NTHR) {
            int r = li >> 8, c = li & 255;
            sWd[r * 257 + c] = wdec[(o0 + r) * HID + k0 + c];
        }
        __syncthreads();
        if (tid < 128) {
#pragma unroll 8
            for (int k = 0; k < 256; k++)
                acc += sh2[b * 257 + k] * sWd[oo * 257 + k];
        }
    }
    if (tid < 128)
        outp[b * OUTW + toff + o0 + oo] = acc + bdec[o0 + oo];
}

// ---------------- prep 1: quantize + tile everything ----------------
__global__ void k_prep1(
    const float* __restrict__ wih1, const float* __restrict__ whh1,
    const float* __restrict__ wih2, const float* __restrict__ whh2,
    const float* __restrict__ wih3, const float* __restrict__ whh3,
    const float* __restrict__ seq,
    const float* __restrict__ bi1, const float* __restrict__ bh1,
    const float* __restrict__ bi2, const float* __restrict__ bh2,
    const float* __restrict__ bi3, const float* __restrict__ bh3)
{
    const long i0 = (long)blockIdx.x * blockDim.x + threadIdx.x;
    const long stride = (long)gridDim.x * blockDim.x;

    // A) main weight tiles: iterate [m][jb][kb][tr][144]; write both planes
    for (long i = i0; i < 6L * 32 * 8 * 128 * 144; i += stride) {
        int cc = (int)(i % 144); long t1 = i / 144;
        int tr = (int)(t1 % 128); long t2 = t1 / 128;
        int kb = (int)(t2 % 8); long t3 = t2 / 8;
        int jbb = (int)(t3 % 32);
        int m = (int)(t3 / 32);
        unsigned char* wq = &g_WQ[m][jbb][kb][0][0][0];
        const int off = tr * 144 + cc;
        if (cc >= 128) { wq[off] = 0; wq[PLW + off] = 0; continue; }
        if (m == 5) continue;   // Mw filled by k_mw
        const float* p = (m == 0) ? whh1 : (m == 1) ? wih2 : (m == 2) ? whh2
                                 : (m == 3) ? wih3 : whh3;
        int row = ((tr >> 5) << 10) + jbb * 32 + (tr & 31);
        int k = kb * 128 + cc;
        float sc = (m == 0) ? 65536.0f : 524288.0f;   // L0: 2^16, L1/2: 2^19
        signed char h, l2;
        q2p(p[(long)row * HID + k], sc, &h, &l2);
        wq[off] = (unsigned char)h; wq[PLW + off] = (unsigned char)l2;
    }
    // B) W1 tiles (K padded 132 -> 256)
    for (long i = i0; i < 32L * 2 * 128 * 144; i += stride) {
        int cc = (int)(i % 144); long t1 = i / 144;
        int tr = (int)(t1 % 128); long t2 = t1 / 128;
        int kb = (int)(t2 % 2); int jbb = (int)(t2 / 2);
        unsigned char* wq = &g_W1Q[jbb][kb][0][0][0];
        const int off = tr * 144 + cc;
        int k = kb * 128 + cc;
        float v = (cc < 128 && k < IND) ?
            wih1[(long)(((tr >> 5) << 10) + jbb * 32 + (tr & 31)) * IND + k] : 0.0f;
        signed char h, l2;
        q2p(v, 65536.0f, &h, &l2);                    // L0 scale
        wq[off] = (unsigned char)h; wq[PLW + off] = (unsigned char)l2;
    }
    // C) frames quantized, tiled
    for (long i = i0; i < (long)NT * 2 * 32 * 144; i += stride) {
        int cc = (int)(i % 144); long t1 = i / 144;
        int b = (int)(t1 % 32); long t2 = t1 / 32;
        int kb = (int)(t2 % 2); int t = (int)(t2 / 2);
        unsigned char* xq = &g_xQ[t][kb][0][0][0];
        const int off = b * 144 + cc;
        int k = kb * 128 + cc;
        float v = (cc < 128 && k < IND) ? seq[((long)b * NT + t) * IND + k] : 0.0f;
        signed char h, l2;
        q2p(v, 4096.0f, &h, &l2);
        xq[off] = (unsigned char)h; xq[PLA + off] = (unsigned char)l2;
    }
    // D) biases
    for (long i = i0; i < 3L * G4; i += stride) {
        int l = (int)(i >> 12), r = (int)(i & 4095);
        const float* pi = (l == 0) ? bi1 : (l == 1) ? bi2 : bi3;
        const float* ph = (l == 0) ? bh1 : (l == 1) ? bh2 : bh3;
        g_bs[l][r] = pi[r] + ph[r];
    }
    // E) zero state
    for (long i = i0; i < 3L * NB * HID; i += stride) (&g_c[0][0][0])[i] = 0.0f;
    for (long i = i0; i < 2L * 3 * NB * HID; i += stride) (&g_hf[0][0][0][0])[i] = 0.0f;
    for (long i = i0; i < 2L * 3 * 8 * 2 * 32 * 144; i += stride)
        (&g_hQ[0][0][0][0][0][0])[i] = 0;
}

// ---------------- prep 2: Mw = W_ih1 @ W_dec (quantized out) + bsM ----------------
__global__ void k_mw(const float* __restrict__ wih1, const float* __restrict__ wdec,
                     const float* __restrict__ bdec)
{
    extern __shared__ __align__(16) char smraw[];
    const int tid = threadIdx.x, bid = blockIdx.x;

    if (bid >= 512) {
        int r = (bid - 512) * 256 + tid;
        float a = 0.0f;
        for (int j = 0; j < IND; j++) a += wih1[r * IND + j] * bdec[j];
        g_bsM[r] = g_bs[0][r] + a;
        return;
    }
    float* sW1 = (float*)smraw;              // [128][133]
    float* sWd = (float*)smraw + 128 * 133;  // [132][64]
    const int r0 = (bid >> 4) * 128;
    const int c0 = (bid & 15) * 64;

    for (int li = tid; li < 128 * IND; li += 256) {
        int rr = li / IND, jj = li % IND;
        sW1[rr * 133 + jj] = wih1[(r0 + rr) * IND + jj];
    }
    for (int li = tid; li < IND * 64; li += 256) {
        int j = li >> 6, cc = li & 63;
        sWd[j * 64 + cc] = wdec[j * HID + c0 + cc];
    }
    __syncthreads();

    const int ty = tid >> 4, tx = tid & 15;
    float a[8][4];
#pragma unroll
    for (int i = 0; i < 8; i++)
#pragma unroll
        for (int q = 0; q < 4; q++) a[i][q] = 0.0f;

    for (int j = 0; j < IND; j++) {
        float4 wd = *(const float4*)&sWd[j * 64 + tx * 4];
#pragma unroll
        for (int i = 0; i < 8; i++) {
            float w1 = sW1[(ty + 16 * i) * 133 + j];
            a[i][0] += w1 * wd.x; a[i][1] += w1 * wd.y;
            a[i][2] += w1 * wd.z; a[i][3] += w1 * wd.w;
        }
    }
#pragma unroll
    for (int i = 0; i < 8; i++)
#pragma unroll
        for (int q = 0; q < 4; q++) {
            int r = r0 + ty + 16 * i, c = c0 + tx * 4 + q;
            int gate = r >> 10, win = r & 1023;
            int jbb = win >> 5, tr = gate * 32 + (win & 31);
            int kb = c >> 7, cc = c & 127;
            unsigned char* wq = &g_WQ[5][jbb][kb][0][0][0];
            signed char h, l2;
            q2p(a[i][q], 65536.0f, &h, &l2);   // L0 scale
            wq[tr * 144 + cc] = (unsigned char)h;
            wq[PLW + tr * 144 + cc] = (unsigned char)l2;
        }
}

// ---------------- persistent kernel: all 100 steps ----------------
// gate blocks: warps 0..7 = IMMA consumers, warp 8 = bulk-copy producer
__global__ void __launch_bounds__(NTHR, 1)
k_all(const float* __restrict__ wdec, const float* __restrict__ bdec,
      float* __restrict__ dout)
{
    extern __shared__ __align__(16) char smraw[];
    const int tid = threadIdx.x, bid = blockIdx.x;

    if (bid >= 96) {   // ---- decoder blocks ----
        const int db = bid - 96;
        for (int t = 0; t < NT; t++) {
            if (t > 0)
                dec_core((float*)smraw, db, tid, &g_hf[(t & 1) ^ 1][2][0][0],
                         wdec, bdec, dout, (t - 1) * IND);
            gridbar();
        }
        dec_core((float*)smraw, db, tid, &g_hf[1][2][0][0], wdec, bdec, dout, 99 * IND);
        return;
    }

    // ---- gate blocks ----
    const int l = bid >> 5, jb = bid & 31, j0 = jb << 5;
    const int lane = tid & 31, w = tid >> 5;     // w: 0..8
    const unsigned smb = sptr(smraw);
    const unsigned fullB = smb + CTRL;           // 4 x 8B
    const unsigned emptyB = smb + CTRL + 32;     // 4 x 8B
    const float invS = (l == 0) ? 0x1p-28f : 0x1p-31f;   // 1/(Sw*Sa)

    if (tid == 0) {
        for (int s = 0; s < DEPTH; s++) { mbar_init(fullB + s * 8, 1); mbar_init(emptyB + s * 8, 8); }
    }
    fence_async();
    __syncthreads();

    int sg = 0;
    for (int t = 0; t < NT; t++) {
        const int prev = (t & 1) ^ 1, cur = t & 1;
        const int gt = (t % 10) < 5;

        const char *Wt0, *Wt1, *At0, *At1;
        int nst1;
        if (l == 0) {
            if (gt) {
                Wt0 = (const char*)&g_W1Q[jb][0][0][0][0];
                At0 = (const char*)&g_xQ[t][0][0][0][0];
                nst1 = 2;
            } else {
                Wt0 = (const char*)&g_WQ[5][jb][0][0][0][0];
                At0 = (const char*)&g_hQ[prev][2][0][0][0][0];
                nst1 = 8;
            }
            Wt1 = (const char*)&g_WQ[0][jb][0][0][0][0];
            At1 = (const char*)&g_hQ[prev][0][0][0][0][0];
        } else if (l == 1) {
            Wt0 = (const char*)&g_WQ[1][jb][0][0][0][0];
            At0 = (const char*)&g_hQ[prev][0][0][0][0][0];
            Wt1 = (const char*)&g_WQ[2][jb][0][0][0][0];
            At1 = (const char*)&g_hQ[prev][1][0][0][0][0];
            nst1 = 8;
        } else {
            Wt0 = (const char*)&g_WQ[3][jb][0][0][0][0];
            At0 = (const char*)&g_hQ[prev][1][0][0][0][0];
            Wt1 = (const char*)&g_WQ[4][jb][0][0][0][0];
            At1 = (const char*)&g_hQ[prev][2][0][0][0][0];
            nst1 = 8;
        }
        const int nst = nst1 + 8;

        if (w == 8) {
            // ---- producer warp: bulk copies ----
            if (lane == 0) {
                for (int s = 0; s < nst; s++) {
                    const int g = sg + s;
                    const int slot = g % DEPTH, u = g / DEPTH;
                    if (u > 0) mbar_wait(emptyB + slot * 8, (u - 1) & 1);
                    const int seg = (s >= nst1);
                    const int kb = seg ? (s - nst1) : s;
                    const unsigned d = smb + slot * SLOT;
                    const unsigned fb = fullB + slot * 8;
                    mbar_expect(fb, TXB);
                    bulkcp(d, (seg ? Wt1 : Wt0) + (long)kb * TILE_W, TILE_W, fb);
                    bulkcp(d + OF_A, (seg ? At1 : At0) + (long)kb * TILE_A, TILE_A, fb);
                }
            }
        } else {
            // ---- consumer warps: s8 dual-plane IMMA ----
            int dHH[2][2][4], dM[2][2][4], dLL[2][2][4];
#pragma unroll
            for (int a = 0; a < 2; a++)
#pragma unroll
                for (int b = 0; b < 2; b++)
#pragma unroll
                    for (int c = 0; c < 4; c++) { dHH[a][b][c] = 0; dM[a][b][c] = 0; dLL[a][b][c] = 0; }

            for (int s = 0; s < nst; s++) {
                const int g = sg + s, slot = g % DEPTH;
                mbar_wait(fullB + slot * 8, (g / DEPTH) & 1);

                const char* sb = smraw + slot * SLOT;
                const char* Ab = sb + OF_A;
                const char* Bb = sb;

#pragma unroll
                for (int cb = 0; cb < 128; cb += 32) {
                    unsigned af[2][2][4];   // [mi][plane]
#pragma unroll
                    for (int mi = 0; mi < 2; mi++)
#pragma unroll
                        for (int p = 0; p < 2; p++)
                            ldmX4(af[mi][p], sptr(Ab + (mi * 16 + (lane & 15)) * 144 +
                                                  p * PLA + cb + ((lane >> 4) << 4)));
                    unsigned bf[2][4];      // [plane]{nf0k0,nf0k1,nf1k0,nf1k1}
                    const int brow = w * 16 + ((lane >> 4) << 3) + (lane & 7);
                    const int bco = cb + (((lane >> 3) & 1) << 4);
#pragma unroll
                    for (int p = 0; p < 2; p++)
                        ldmX4(bf[p], sptr(Bb + brow * 144 + p * PLW + bco));
#pragma unroll
                    for (int mi = 0; mi < 2; mi++)
#pragma unroll
                        for (int nf = 0; nf < 2; nf++) {
                            imma(dHH[mi][nf], af[mi][0], bf[0][nf * 2], bf[0][nf * 2 + 1]);
                            imma(dM[mi][nf],  af[mi][0], bf[1][nf * 2], bf[1][nf * 2 + 1]);
                            imma(dM[mi][nf],  af[mi][1], bf[0][nf * 2], bf[0][nf * 2 + 1]);
                            imma(dLL[mi][nf], af[mi][1], bf[1][nf * 2], bf[1][nf * 2 + 1]);
                        }
                }
                if (lane == 0) mbar_arrive(emptyB + slot * 8);
            }

            // stage gates + bias into smem
            __syncthreads();
            float* G = (float*)smraw;   // [32][129] fp32
#pragma unroll
            for (int mi = 0; mi < 2; mi++)
#pragma unroll
                for (int nf = 0; nf < 2; nf++)
#pragma unroll
                    for (int r = 0; r < 4; r++) {
                        int m = mi * 16 + (lane >> 2) + ((r >> 1) << 3);
                        int n = (w << 4) + (nf << 3) + ((lane & 3) << 1) + (r & 1);
                        int row = growf(n, j0);
                        float bias = (l == 0 && !gt) ? g_bsM[row] : g_bs[l][row];
                        float v = (float)dHH[mi][nf][r] * 65536.0f +
                                  (float)dM[mi][nf][r] * 256.0f +
                                  (float)dLL[mi][nf][r];
                        G[m * 129 + n] = v * invS + bias;
                    }
        }
        if (w == 8) __syncthreads();   // producer joins the pre-G barrier
        __syncthreads();

        // ---- pointwise LSTM update (first 256 threads) ----
        if (tid < 256) {
            const int b = tid >> 3;
            const int jj0 = (tid & 7) << 2;
#pragma unroll
            for (int q = 0; q < 4; q++) {
                const int jj = jj0 + q, j = j0 + jj;
                float* G = (float*)smraw;
                float gi = G[b * 129 + jj];
                float gf = G[b * 129 + 32 + jj];
                float gg = G[b * 129 + 64 + jj];
                float go = G[b * 129 + 96 + jj];
                float c0 = g_c[l][b][j];
                float cn = sigm(gf) * c0 + sigm(gi) * tanhf(gg);
                float hn = sigm(go) * tanhf(cn);
                g_c[l][b][j] = cn;
                g_hf[cur][l][b][j] = hn;
                const int kb = j >> 7, cc = j & 127;
                unsigned char* hq = &g_hQ[cur][l][kb][0][0][0];
                signed char hh, hl;
                q2p(hn, 4096.0f, &hh, &hl);
                hq[b * 144 + cc] = (unsigned char)hh;
                hq[PLA + b * 144 + cc] = (unsigned char)hl;
            }
        }
        fence_async();   // order generic smem writes before next step's bulk copies
        sg += nst;
        gridbar();
    }
}

// ---------------- host ----------------
#define MW_SMEM 101888

extern "C" void kernel_launch(void* const* d_in, const int* in_sizes, int n_in,
                              void* d_out, int out_size) {
    (void)in_sizes; (void)n_in; (void)out_size;
    const float* seq  = (const float*)d_in[0];
    const float* Wih1 = (const float*)d_in[1];
    const float* Whh1 = (const float*)d_in[2];
    const float* bih1 = (const float*)d_in[3];
    const float* bhh1 = (const float*)d_in[4];
    const float* Wih2 = (const float*)d_in[5];
    const float* Whh2 = (const float*)d_in[6];
    const float* bih2 = (const float*)d_in[7];
    const float* bhh2 = (const float*)d_in[8];
    const float* Wih3 = (const float*)d_in[9];
    const float* Whh3 = (const float*)d_in[10];
    const float* bih3 = (const float*)d_in[11];
    const float* bhh3 = (const float*)d_in[12];
    const float* Wdec = (const float*)d_in[13];
    const float* bdec = (const float*)d_in[14];
    float* out = (float*)d_out;

    cudaFuncSetAttribute(k_all, cudaFuncAttributeMaxDynamicSharedMemorySize, SMEM_ALL);
    cudaFuncSetAttribute(k_mw, cudaFuncAttributeMaxDynamicSharedMemorySize, MW_SMEM);

    k_prep1<<<2048, 256>>>(Wih1, Whh1, Wih2, Whh2, Wih3, Whh3, seq,
                           bih1, bhh1, bih2, bhh2, bih3, bhh3);
    k_mw<<<528, 256, MW_SMEM>>>(Wih1, Wdec, bdec);
    k_all<<<NBLK, NTHR, SMEM_ALL>>>(Wdec, bdec, out);
}

// round 14
// speedup vs baseline: 2.8071x; 2.8071x over previous
#include <cuda_runtime.h>
#include <cuda_fp16.h>
#include <cuda_fp8.h>
#include <math.h>

#define HID   1024
#define G4    4096
#define NB    32
#define NT    100
#define IND   132
#define OUTW  13200
#define NBLK  129
#define NTHR  288
#define LO_SCALE 16384.0f
#define LO_I     (1.0f/16384.0f)

// K=128 stage tiles (bytes)
#define TILE_WH 34816   // 128 rows x 136 halves fp16
#define TILE_W8 18432   // 128 rows x 144 bytes fp8
#define TILE_A  8704    // 32 rows x 136 halves fp16
#define SLOT    61952
#define OF_W8   34816
#define OF_AH   53248
#define DEPTH   3
#define CTRL    185856  // 3*SLOT
#define OF_G    185920  // G staging area (32*129*4 = 16512 B)
#define SMEM_ALL 202432
#define TXB     61952
#define PF      2       // stages of weight prefetch across gridbar

// ---------------- persistent device scratch (pre-tiled, K=128 tiles) ----------------
// weight tiles: [matrix][jb][kb][row 128][136]  row = gate*32 + r, col = kb*128 + c
// matrices: 0 Whh1, 1 Wih2, 2 Whh2, 3 Wih3, 4 Whh3, 5 Mw(=Wih1@Wdec)
__device__ __half         g_WT[6][32][8][128][136];
__device__ unsigned char  g_W8T[6][32][8][128][144];  // fp8 e4m3 lo * 2^14, perm8 layout
__device__ __half         g_W1T[32][2][128][136];     // Wih1 padded to K=256
__device__ unsigned char  g_W18T[32][2][128][144];
__device__ __half         g_xhT[NT][2][32][136];      // frames, tiled
__device__ __half         g_hhT[2][3][8][32][136];    // h (fp16), tiled per kb
__device__ float          g_hf[2][3][NB][HID];        // fp32 h for decoder
__device__ float          g_c[3][NB][HID];
__device__ float          g_bs[3][G4];
__device__ float          g_bsM[G4];
__device__ unsigned       g_bar;

// perm within 16-byte group so a thread's fp8 fragment is one LDS.u32
__device__ __forceinline__ int perm8(int k) {
    int g = k >> 4, i = k & 15;
    return (g << 4) | (((i & 7) >> 1) << 2) | (((i >> 3) & 1) << 1) | (i & 1);
}

// ---------------- asm helpers ----------------
__device__ __forceinline__ unsigned sptr(const void* p) {
    return (unsigned)__cvta_generic_to_shared(p);
}
__device__ __forceinline__ void bulkcp(unsigned dst, const void* src, unsigned bytes,
                                       unsigned mbar) {
    asm volatile(
        "cp.async.bulk.shared::cluster.global.mbarrier::complete_tx::bytes "
        "[%0], [%1], %2, [%3];"
        :: "r"(dst), "l"(src), "r"(bytes), "r"(mbar) : "memory");
}
__device__ __forceinline__ void mbar_init(unsigned a, unsigned cnt) {
    asm volatile("mbarrier.init.shared.b64 [%0], %1;" :: "r"(a), "r"(cnt) : "memory");
}
__device__ __forceinline__ void mbar_expect(unsigned a, unsigned tx) {
    asm volatile("mbarrier.arrive.expect_tx.shared.b64 _, [%0], %1;"
                 :: "r"(a), "r"(tx) : "memory");
}
__device__ __forceinline__ void mbar_arrive(unsigned a) {
    asm volatile("mbarrier.arrive.shared.b64 _, [%0];" :: "r"(a) : "memory");
}
__device__ __forceinline__ void mbar_wait(unsigned a, unsigned par) {
    asm volatile(
        "{\n\t.reg .pred P;\n\t"
        "W_%=:\n\t"
        "mbarrier.try_wait.parity.acquire.cta.shared::cta.b64 P, [%0], %1, 0x989680;\n\t"
        "@P bra.uni D_%=;\n\t"
        "bra.uni W_%=;\n\t"
        "D_%=:\n\t}"
        :: "r"(a), "r"(par) : "memory");
}
__device__ __forceinline__ void fence_async() {
    asm volatile("fence.proxy.async.shared::cta;" ::: "memory");
}
__device__ __forceinline__ void ldmA4(unsigned a[4], unsigned addr) {
    asm volatile("ldmatrix.sync.aligned.m8n8.x4.shared.b16 {%0,%1,%2,%3}, [%4];"
                 : "=r"(a[0]), "=r"(a[1]), "=r"(a[2]), "=r"(a[3]) : "r"(addr));
}
__device__ __forceinline__ void ldmB2(unsigned b[2], unsigned addr) {
    asm volatile("ldmatrix.sync.aligned.m8n8.x2.shared.b16 {%0,%1}, [%2];"
                 : "=r"(b[0]), "=r"(b[1]) : "r"(addr));
}
__device__ __forceinline__ void mma16816(float c[4], const unsigned a[4], const unsigned b[2]) {
    asm volatile("mma.sync.aligned.m16n8k16.row.col.f32.f16.f16.f32 "
                 "{%0,%1,%2,%3}, {%4,%5,%6,%7}, {%8,%9}, {%0,%1,%2,%3};"
                 : "+f"(c[0]), "+f"(c[1]), "+f"(c[2]), "+f"(c[3])
                 : "r"(a[0]), "r"(a[1]), "r"(a[2]), "r"(a[3]), "r"(b[0]), "r"(b[1]));
}
__device__ __forceinline__ unsigned cvt8x2(unsigned short v) {
    unsigned r;
    asm("cvt.rn.f16x2.e4m3x2 %0, %1;" : "=r"(r) : "h"(v));
    return r;
}
__device__ __forceinline__ float sigm(float x) { return 1.0f / (1.0f + __expf(-x)); }
__device__ __forceinline__ int growf(int n, int j0) { return ((n >> 5) << 10) + j0 + (n & 31); }

// step descriptor (which tiles feed this layer at step t)
struct SDesc {
    const char *Wt0, *Wt1, *W8t0, *W8t1, *At0, *At1;
    int nst1;
};
__device__ __forceinline__ void get_desc(int l, int jb, int t, SDesc& d) {
    const int prev = (t & 1) ^ 1;
    const int gt = (t % 10) < 5;
    if (l == 0) {
        if (gt) {
            d.Wt0 = (const char*)&g_W1T[jb][0][0][0];
            d.W8t0 = (const char*)&g_W18T[jb][0][0][0];
            d.At0 = (const char*)&g_xhT[t][0][0][0];
            d.nst1 = 2;
        } else {
            d.Wt0 = (const char*)&g_WT[5][jb][0][0][0];
            d.W8t0 = (const char*)&g_W8T[5][jb][0][0][0];
            d.At0 = (const char*)&g_hhT[prev][2][0][0][0];
            d.nst1 = 8;
        }
        d.Wt1 = (const char*)&g_WT[0][jb][0][0][0];
        d.W8t1 = (const char*)&g_W8T[0][jb][0][0][0];
        d.At1 = (const char*)&g_hhT[prev][0][0][0][0];
    } else if (l == 1) {
        d.Wt0 = (const char*)&g_WT[1][jb][0][0][0];
        d.W8t0 = (const char*)&g_W8T[1][jb][0][0][0];
        d.At0 = (const char*)&g_hhT[prev][0][0][0][0];
        d.Wt1 = (const char*)&g_WT[2][jb][0][0][0];
        d.W8t1 = (const char*)&g_W8T[2][jb][0][0][0];
        d.At1 = (const char*)&g_hhT[prev][1][0][0][0];
        d.nst1 = 8;
    } else {
        d.Wt0 = (const char*)&g_WT[3][jb][0][0][0];
        d.W8t0 = (const char*)&g_W8T[3][jb][0][0][0];
        d.At0 = (const char*)&g_hhT[prev][1][0][0][0];
        d.Wt1 = (const char*)&g_WT[4][jb][0][0][0];
        d.W8t1 = (const char*)&g_W8T[4][jb][0][0][0];
        d.At1 = (const char*)&g_hhT[prev][2][0][0][0];
        d.nst1 = 8;
    }
}

// ---------------- grid barrier ----------------
__device__ __forceinline__ void gridbar() {
    __syncthreads();
    if (threadIdx.x == 0) {
        __threadfence();
        unsigned gen = atomicAdd(&g_bar, 1u);
        unsigned target = gen - (gen % NBLK) + NBLK;
        while (*(volatile unsigned*)&g_bar < target) { }
        __threadfence();
    }
    __syncthreads();
}

// ---------------- decoder core (288-thread block) ----------------
__device__ void dec_core(float* smf, int db, int tid,
                         const float* __restrict__ h2, const float* __restrict__ wdec,
                         const float* __restrict__ bdec, float* __restrict__ outp, int toff)
{
    float* sh2 = smf;
    float* sWd = smf + 32 * 257;
    const int o0 = db * 4;
    const int oo = tid & 3, b = (tid >> 2) & 31;
    float acc = 0.0f;
    for (int k0 = 0; k0 < HID; k0 += 256) {
        __syncthreads();
        for (int li = tid; li < 8192; li += NTHR) {
            int r = li >> 8, c = li & 255;
            sh2[r * 257 + c] = h2[r * HID + k0 + c];
        }
        for (int li = tid; li < 1024; li += NTHR) {
            int r = li >> 8, c = li & 255;
            sWd[r * 257 + c] = wdec[(o0 + r) * HID + k0 + c];
        }
        __syncthreads();
        if (tid < 128) {
#pragma unroll 8
            for (int k = 0; k < 256; k++)
                acc += sh2[b * 257 + k] * sWd[oo * 257 + k];
        }
    }
    if (tid < 128)
        outp[b * OUTW + toff + o0 + oo] = acc + bdec[o0 + oo];
}

// ---------------- merged prep: tiling + Mw + bsM (one launch) ----------------
// blocks 0..2047: tiling/quantize; 2048..2559: Mw GEMM; 2560..2575: bsM
__global__ void k_prep(
    const float* __restrict__ wih1, const float* __restrict__ whh1,
    const float* __restrict__ wih2, const float* __restrict__ whh2,
    const float* __restrict__ wih3, const float* __restrict__ whh3,
    const float* __restrict__ seq,
    const float* __restrict__ bi1, const float* __restrict__ bh1,
    const float* __restrict__ bi2, const float* __restrict__ bh2,
    const float* __restrict__ bi3, const float* __restrict__ bh3,
    const float* __restrict__ wdec, const float* __restrict__ bdec)
{
    extern __shared__ __align__(16) char smraw[];
    const int tid = threadIdx.x, bid = blockIdx.x;

    if (bid >= 2560) {   // ---- bsM ----
        int r = (bid - 2560) * 256 + tid;
        float a = bi1[r] + bh1[r];
        for (int j = 0; j < IND; j++) a += wih1[r * IND + j] * bdec[j];
        g_bsM[r] = a;
        return;
    }
    if (bid >= 2048) {   // ---- Mw GEMM, tiled output ----
        const int mb = bid - 2048;
        float* sW1 = (float*)smraw;              // [128][133]
        float* sWd = (float*)smraw + 128 * 133;  // [132][64]
        const int r0 = (mb >> 4) * 128;
        const int c0 = (mb & 15) * 64;

        for (int li = tid; li < 128 * IND; li += 256) {
            int rr = li / IND, jj = li % IND;
            sW1[rr * 133 + jj] = wih1[(r0 + rr) * IND + jj];
        }
        for (int li = tid; li < IND * 64; li += 256) {
            int j = li >> 6, cc = li & 63;
            sWd[j * 64 + cc] = wdec[j * HID + c0 + cc];
        }
        __syncthreads();

        const int ty = tid >> 4, tx = tid & 15;
        float a[8][4];
#pragma unroll
        for (int i = 0; i < 8; i++)
#pragma unroll
            for (int q = 0; q < 4; q++) a[i][q] = 0.0f;

        for (int j = 0; j < IND; j++) {
            float4 wd = *(const float4*)&sWd[j * 64 + tx * 4];
#pragma unroll
            for (int i = 0; i < 8; i++) {
                float w1 = sW1[(ty + 16 * i) * 133 + j];
                a[i][0] += w1 * wd.x; a[i][1] += w1 * wd.y;
                a[i][2] += w1 * wd.z; a[i][3] += w1 * wd.w;
            }
        }
#pragma unroll
        for (int i = 0; i < 8; i++)
#pragma unroll
            for (int q = 0; q < 4; q++) {
                int r = r0 + ty + 16 * i, c = c0 + tx * 4 + q;
                float v = a[i][q];
                __half hi = __float2half_rn(v);
                int gate = r >> 10, win = r & 1023;
                int jbb = win >> 5, tr = gate * 32 + (win & 31);
                int kb = c >> 7, cc = c & 127;
                g_WT[5][jbb][kb][tr][cc] = hi;
                unsigned char* w8 = &g_W8T[5][jbb][kb][0][0];
                w8[tr * 144 + perm8(cc)] =
                    __nv_cvt_float_to_fp8((v - __half2float(hi)) * LO_SCALE,
                                          __NV_SATFINITE, __NV_E4M3);
            }
        return;
    }

    // ---- tiling part (blocks 0..2047) ----
    const long i0 = (long)bid * blockDim.x + tid;
    const long stride = 2048L * blockDim.x;

    // A) fp16 weight tiles m=0..5 (data m=0..4; pads for all incl m=5)
    for (long i = i0; i < 6L * 32 * 8 * 128 * 136; i += stride) {
        int cc = (int)(i % 136); long t1 = i / 136;
        int tr = (int)(t1 % 128); long t2 = t1 / 128;
        int kb = (int)(t2 % 8); long t3 = t2 / 8;
        int jbb = (int)(t3 % 32);
        int m = (int)(t3 / 32);
        if (cc >= 128) { g_WT[m][jbb][kb][tr][cc] = __float2half_rn(0.0f); continue; }
        if (m == 5) continue;
        const float* p = (m == 0) ? whh1 : (m == 1) ? wih2 : (m == 2) ? whh2
                                 : (m == 3) ? wih3 : whh3;
        int row = ((tr >> 5) << 10) + jbb * 32 + (tr & 31);
        int k = kb * 128 + cc;
        float v = p[(long)row * HID + k];
        __half hi = __float2half_rn(v);
        g_WT[m][jbb][kb][tr][cc] = hi;
        unsigned char* w8 = &g_W8T[m][jbb][kb][0][0];
        w8[tr * 144 + perm8(cc)] =
            __nv_cvt_float_to_fp8((v - __half2float(hi)) * LO_SCALE,
                                  __NV_SATFINITE, __NV_E4M3);
    }
    // B) fp8 row pads (bytes 128..143) for all m
    for (long i = i0; i < 6L * 32 * 8 * 128 * 16; i += stride) {
        int pb = (int)(i % 16); long t1 = i / 16;
        int tr = (int)(t1 % 128); long t2 = t1 / 128;
        int kb = (int)(t2 % 8); long t3 = t2 / 8;
        int jbb = (int)(t3 % 32); int m = (int)(t3 / 32);
        unsigned char* w8 = &g_W8T[m][jbb][kb][0][0];
        w8[tr * 144 + 128 + pb] = 0;
    }
    // C) W1 tiles (K padded 132->256, 2 kb of 128)
    for (long i = i0; i < 32L * 2 * 128 * 136; i += stride) {
        int cc = (int)(i % 136); long t1 = i / 136;
        int tr = (int)(t1 % 128); long t2 = t1 / 128;
        int kb = (int)(t2 % 2); int jbb = (int)(t2 / 2);
        if (cc >= 128) { g_W1T[jbb][kb][tr][cc] = __float2half_rn(0.0f); continue; }
        int row = ((tr >> 5) << 10) + jbb * 32 + (tr & 31);
        int k = kb * 128 + cc;
        float v = (k < IND) ? wih1[(long)row * IND + k] : 0.0f;
        __half hi = __float2half_rn(v);
        g_W1T[jbb][kb][tr][cc] = hi;
        unsigned char* w8 = &g_W18T[jbb][kb][0][0];
        w8[tr * 144 + perm8(cc)] =
            __nv_cvt_float_to_fp8((v - __half2float(hi)) * LO_SCALE,
                                  __NV_SATFINITE, __NV_E4M3);
    }
    for (long i = i0; i < 32L * 2 * 128 * 16; i += stride) {
        int pb = (int)(i % 16); long t1 = i / 16;
        int tr = (int)(t1 % 128); long t2 = t1 / 128;
        int kb = (int)(t2 % 2); int jbb = (int)(t2 / 2);
        unsigned char* w8 = &g_W18T[jbb][kb][0][0];
        w8[tr * 144 + 128 + pb] = 0;
    }
    // D) frames tiled (fp16 hi only)
    for (long i = i0; i < (long)NT * 2 * 32 * 136; i += stride) {
        int cc = (int)(i % 136); long t1 = i / 136;
        int b = (int)(t1 % 32); long t2 = t1 / 32;
        int kb = (int)(t2 % 2); int t = (int)(t2 / 2);
        float v = 0.0f;
        if (cc < 128) {
            int k = kb * 128 + cc;
            if (k < IND) v = seq[((long)b * NT + t) * IND + k];
        }
        g_xhT[t][kb][b][cc] = __float2half_rn(v);
    }
    // E) biases
    for (long i = i0; i < 3L * G4; i += stride) {
        int l = (int)(i >> 12), r = (int)(i & 4095);
        const float* pi = (l == 0) ? bi1 : (l == 1) ? bi2 : bi3;
        const float* ph = (l == 0) ? bh1 : (l == 1) ? bh2 : bh3;
        g_bs[l][r] = pi[r] + ph[r];
    }
    // F) zero state
    for (long i = i0; i < 3L * NB * HID; i += stride) (&g_c[0][0][0])[i] = 0.0f;
    for (long i = i0; i < 2L * 3 * NB * HID; i += stride) (&g_hf[0][0][0][0])[i] = 0.0f;
    for (long i = i0; i < 2L * 3 * 8 * 32 * 136; i += stride)
        (&g_hhT[0][0][0][0][0])[i] = __float2half_rn(0.0f);
}

// ---------------- persistent kernel: all 100 steps ----------------
// gate blocks: warps 0..7 = MMA consumers, warp 8 = bulk-copy producer
__global__ void __launch_bounds__(NTHR, 1)
k_all(const float* __restrict__ wdec, const float* __restrict__ bdec,
      float* __restrict__ dout)
{
    extern __shared__ __align__(16) char smraw[];
    const int tid = threadIdx.x, bid = blockIdx.x;

    if (bid >= 96) {   // ---- decoder blocks ----
        const int db = bid - 96;
        for (int t = 0; t < NT; t++) {
            if (t > 0)
                dec_core((float*)smraw, db, tid, &g_hf[(t & 1) ^ 1][2][0][0],
                         wdec, bdec, dout, (t - 1) * IND);
            gridbar();
        }
        dec_core((float*)smraw, db, tid, &g_hf[1][2][0][0], wdec, bdec, dout, 99 * IND);
        return;
    }

    // ---- gate blocks ----
    const int l = bid >> 5, jb = bid & 31, j0 = jb << 5;
    const int lane = tid & 31, w = tid >> 5;     // w: 0..8
    const unsigned smb = sptr(smraw);
    const unsigned fullB = smb + CTRL;           // 3 x 8B
    const unsigned emptyB = smb + CTRL + 24;     // 3 x 8B
    float* G = (float*)(smraw + OF_G);           // [32][129] fp32 staging

    if (tid == 0) {
        for (int s = 0; s < DEPTH; s++) { mbar_init(fullB + s * 8, 1); mbar_init(emptyB + s * 8, 8); }
    }
    fence_async();
    __syncthreads();

    int sg = 0;
    for (int t = 0; t < NT; t++) {
        const int cur = t & 1;
        const int gt = (t % 10) < 5;
        SDesc d;
        get_desc(l, jb, t, d);
        const int nst = d.nst1 + 8;

        if (w == 8) {
            // ---- producer warp ----
            if (lane == 0) {
                const int pfStart = (t == 0) ? 0 : PF;
                // A copies for W-prefetched stages (their full barrier already
                // expects the whole TXB; W tiles were issued before gridbar)
                for (int s = 0; s < pfStart; s++) {
                    const int g = sg + s, slot = g % DEPTH;
                    bulkcp(smb + slot * SLOT + OF_AH, d.At0 + (long)s * TILE_A,
                           TILE_A, fullB + slot * 8);
                }
                for (int s = pfStart; s < nst; s++) {
                    const int g = sg + s;
                    const int slot = g % DEPTH, u = g / DEPTH;
                    if (u > 0) mbar_wait(emptyB + slot * 8, (u - 1) & 1);
                    const int seg = (s >= d.nst1);
                    const int kb = seg ? (s - d.nst1) : s;
                    const unsigned dst = smb + slot * SLOT;
                    const unsigned fb = fullB + slot * 8;
                    mbar_expect(fb, TXB);
                    bulkcp(dst, (seg ? d.Wt1 : d.Wt0) + (long)kb * TILE_WH, TILE_WH, fb);
                    bulkcp(dst + OF_W8, (seg ? d.W8t1 : d.W8t0) + (long)kb * TILE_W8,
                           TILE_W8, fb);
                    bulkcp(dst + OF_AH, (seg ? d.At1 : d.At0) + (long)kb * TILE_A,
                           TILE_A, fb);
                }
                // prefetch next step's weight tiles across the grid barrier
                if (t + 1 < NT) {
                    SDesc dn;
                    get_desc(l, jb, t + 1, dn);
                    for (int s = 0; s < PF; s++) {
                        const int g = sg + nst + s;
                        const int slot = g % DEPTH, u = g / DEPTH;
                        if (u > 0) mbar_wait(emptyB + slot * 8, (u - 1) & 1);
                        const unsigned dst = smb + slot * SLOT;
                        const unsigned fb = fullB + slot * 8;
                        mbar_expect(fb, TXB);
                        bulkcp(dst, dn.Wt0 + (long)s * TILE_WH, TILE_WH, fb);
                        bulkcp(dst + OF_W8, dn.W8t0 + (long)s * TILE_W8, TILE_W8, fb);
                    }
                }
            }
        } else {
            // ---- consumer warps: MMA ----
            float accH[2][2][4], accL[2][2][4];
#pragma unroll
            for (int a = 0; a < 2; a++)
#pragma unroll
                for (int b = 0; b < 2; b++)
#pragma unroll
                    for (int c = 0; c < 4; c++) { accH[a][b][c] = 0.0f; accL[a][b][c] = 0.0f; }

            for (int s = 0; s < nst; s++) {
                const int g = sg + s, slot = g % DEPTH;
                mbar_wait(fullB + slot * 8, (g / DEPTH) & 1);

                const char* sb = smraw + slot * SLOT;
                const __half* Abh = (const __half*)(sb + OF_AH);
                const __half* Bbh = (const __half*)sb;
                const unsigned char* Bb8 = (const unsigned char*)(sb + OF_W8);

#pragma unroll
                for (int kk = 0; kk < 128; kk += 16) {
                    unsigned ah0[4], ah1[4];
                    const int aoff = (lane & 15) * 136 + kk + ((lane >> 4) << 3);
                    ldmA4(ah0, sptr(Abh + aoff));
                    ldmA4(ah1, sptr(Abh + 16 * 136 + aoff));
#pragma unroll
                    for (int nf = 0; nf < 2; nf++) {
                        unsigned bh[2], bl[2];
                        const int boff = ((w << 4) + (nf << 3) + (lane & 7)) * 136 +
                                         kk + (((lane >> 3) & 1) << 3);
                        ldmB2(bh, sptr(Bbh + boff));
                        unsigned u = *(const unsigned*)(Bb8 +
                                      ((w << 4) + (nf << 3) + (lane >> 2)) * 144 +
                                      kk + ((lane & 3) << 2));
                        bl[0] = cvt8x2((unsigned short)(u & 0xffffu));
                        bl[1] = cvt8x2((unsigned short)(u >> 16));
                        mma16816(accH[0][nf], ah0, bh);
                        mma16816(accH[1][nf], ah1, bh);
                        mma16816(accL[0][nf], ah0, bl);
                        mma16816(accL[1][nf], ah1, bl);
                    }
                }
                if (lane == 0) mbar_arrive(emptyB + slot * 8);
            }

            // stage gates + bias into dedicated G area
#pragma unroll
            for (int mi = 0; mi < 2; mi++)
#pragma unroll
                for (int nf = 0; nf < 2; nf++)
#pragma unroll
                    for (int r = 0; r < 4; r++) {
                        int m = mi * 16 + (lane >> 2) + ((r >> 1) << 3);
                        int n = (w << 4) + (nf << 3) + ((lane & 3) << 1) + (r & 1);
                        int row = growf(n, j0);
                        float bias = (l == 0 && !gt) ? g_bsM[row] : g_bs[l][row];
                        G[m * 129 + n] = accH[mi][nf][r] + accL[mi][nf][r] * LO_I + bias;
                    }
        }
        __syncthreads();

        // ---- pointwise LSTM update (first 256 threads) ----
        if (tid < 256) {
            const int b = tid >> 3;
            const int jj0 = (tid & 7) << 2;
#pragma unroll
            for (int q = 0; q < 4; q++) {
                const int jj = jj0 + q, j = j0 + jj;
                float gi = G[b * 129 + jj];
                float gf = G[b * 129 + 32 + jj];
                float gg = G[b * 129 + 64 + jj];
                float go = G[b * 129 + 96 + jj];
                float c0 = g_c[l][b][j];
                float cn = sigm(gf) * c0 + sigm(gi) * tanhf(gg);
                float hn = sigm(go) * tanhf(cn);
                g_c[l][b][j] = cn;
                g_hf[cur][l][b][j] = hn;
                const int kb = j >> 7, cc = j & 127;
                g_hhT[cur][l][kb][b][cc] = __float2half_rn(hn);
            }
        }
        fence_async();
        sg += nst;
        gridbar();
    }
}

// ---------------- host ----------------
#define MW_SMEM 101888

extern "C" void kernel_launch(void* const* d_in, const int* in_sizes, int n_in,
                              void* d_out, int out_size) {
    (void)in_sizes; (void)n_in; (void)out_size;
    const float* seq  = (const float*)d_in[0];
    const float* Wih1 = (const float*)d_in[1];
    const float* Whh1 = (const float*)d_in[2];
    const float* bih1 = (const float*)d_in[3];
    const float* bhh1 = (const float*)d_in[4];
    const float* Wih2 = (const float*)d_in[5];
    const float* Whh2 = (const float*)d_in[6];
    const float* bih2 = (const float*)d_in[7];
    const float* bhh2 = (const float*)d_in[8];
    const float* Wih3 = (const float*)d_in[9];
    const float* Whh3 = (const float*)d_in[10];
    const float* bih3 = (const float*)d_in[11];
    const float* bhh3 = (const float*)d_in[12];
    const float* Wdec = (const float*)d_in[13];
    const float* bdec = (const float*)d_in[14];
    float* out = (float*)d_out;

    cudaFuncSetAttribute(k_all, cudaFuncAttributeMaxDynamicSharedMemorySize, SMEM_ALL);
    cudaFuncSetAttribute(k_prep, cudaFuncAttributeMaxDynamicSharedMemorySize, MW_SMEM);

    k_prep<<<2576, 256, MW_SMEM>>>(Wih1, Whh1, Wih2, Whh2, Wih3, Whh3, seq,
                                   bih1, bhh1, bih2, bhh2, bih3, bhh3, Wdec, bdec);
    k_all<<<NBLK, NTHR, SMEM_ALL>>>(Wdec, bdec, out);
}

// round 15
// speedup vs baseline: 3.6655x; 1.3058x over previous
#include <cuda_runtime.h>
#include <cuda_fp16.h>
#include <cuda_fp8.h>
#include <math.h>

#define HID   1024
#define G4    4096
#define NB    32
#define NT    100
#define IND   132
#define OUTW  13200
#define NBLK  129
#define NTHR  544
#define LO_SCALE 16384.0f
#define LO_I     (1.0f/16384.0f)

// K=128 stage tiles (bytes)
#define TILE_WH 34816   // 128 rows x 136 halves fp16
#define TILE_W8 18432   // 128 rows x 144 bytes fp8
#define TILE_A  8704    // 32 rows x 136 halves fp16
#define SLOT    61952
#define OF_W8   34816
#define OF_AH   53248
#define DEPTH   3
#define CTRL    185856  // 3*SLOT
#define OF_G    185920  // G staging area (32*129*4 = 16512 B)
#define SMEM_ALL 202432
#define TXB     61952

// ---------------- persistent device scratch (pre-tiled, K=128 tiles) ----------------
// weight tiles: [matrix][jb][kb][row 128][136]  row = gate*32 + r, col = kb*128 + c
// matrices: 0 Whh1, 1 Wih2, 2 Whh2, 3 Wih3, 4 Whh3, 5 Mw(=Wih1@Wdec)
__device__ __half         g_WT[6][32][8][128][136];
__device__ unsigned char  g_W8T[6][32][8][128][144];  // fp8 e4m3 lo * 2^14, perm8 layout
__device__ __half         g_W1T[32][2][128][136];     // Wih1 padded to K=256
__device__ unsigned char  g_W18T[32][2][128][144];
__device__ __half         g_xhT[NT][2][32][136];      // frames, tiled
__device__ __half         g_hhT[2][3][8][32][136];    // h (fp16), tiled per kb
__device__ float          g_hf[2][3][NB][HID];        // fp32 h for decoder
__device__ float          g_c[3][NB][HID];
__device__ float          g_bs[3][G4];
__device__ float          g_bsM[G4];
__device__ unsigned       g_bar;

// perm within 16-byte group so a thread's fp8 fragment is one LDS.u32
__device__ __forceinline__ int perm8(int k) {
    int g = k >> 4, i = k & 15;
    return (g << 4) | (((i & 7) >> 1) << 2) | (((i >> 3) & 1) << 1) | (i & 1);
}

// ---------------- asm helpers ----------------
__device__ __forceinline__ unsigned sptr(const void* p) {
    return (unsigned)__cvta_generic_to_shared(p);
}
__device__ __forceinline__ void bulkcp(unsigned dst, const void* src, unsigned bytes,
                                       unsigned mbar) {
    asm volatile(
        "cp.async.bulk.shared::cluster.global.mbarrier::complete_tx::bytes "
        "[%0], [%1], %2, [%3];"
        :: "r"(dst), "l"(src), "r"(bytes), "r"(mbar) : "memory");
}
__device__ __forceinline__ void mbar_init(unsigned a, unsigned cnt) {
    asm volatile("mbarrier.init.shared.b64 [%0], %1;" :: "r"(a), "r"(cnt) : "memory");
}
__device__ __forceinline__ void mbar_expect(unsigned a, unsigned tx) {
    asm volatile("mbarrier.arrive.expect_tx.shared.b64 _, [%0], %1;"
                 :: "r"(a), "r"(tx) : "memory");
}
__device__ __forceinline__ void mbar_arrive(unsigned a) {
    asm volatile("mbarrier.arrive.shared.b64 _, [%0];" :: "r"(a) : "memory");
}
__device__ __forceinline__ void mbar_wait(unsigned a, unsigned par) {
    asm volatile(
        "{\n\t.reg .pred P;\n\t"
        "W_%=:\n\t"
        "mbarrier.try_wait.parity.acquire.cta.shared::cta.b64 P, [%0], %1, 0x989680;\n\t"
        "@P bra.uni D_%=;\n\t"
        "bra.uni W_%=;\n\t"
        "D_%=:\n\t}"
        :: "r"(a), "r"(par) : "memory");
}
__device__ __forceinline__ void fence_async() {
    asm volatile("fence.proxy.async.shared::cta;" ::: "memory");
}
__device__ __forceinline__ void ldmA4(unsigned a[4], unsigned addr) {
    asm volatile("ldmatrix.sync.aligned.m8n8.x4.shared.b16 {%0,%1,%2,%3}, [%4];"
                 : "=r"(a[0]), "=r"(a[1]), "=r"(a[2]), "=r"(a[3]) : "r"(addr));
}
__device__ __forceinline__ void ldmB2(unsigned b[2], unsigned addr) {
    asm volatile("ldmatrix.sync.aligned.m8n8.x2.shared.b16 {%0,%1}, [%2];"
                 : "=r"(b[0]), "=r"(b[1]) : "r"(addr));
}
__device__ __forceinline__ void mma16816(float c[4], const unsigned a[4], const unsigned b[2]) {
    asm volatile("mma.sync.aligned.m16n8k16.row.col.f32.f16.f16.f32 "
                 "{%0,%1,%2,%3}, {%4,%5,%6,%7}, {%8,%9}, {%0,%1,%2,%3};"
                 : "+f"(c[0]), "+f"(c[1]), "+f"(c[2]), "+f"(c[3])
                 : "r"(a[0]), "r"(a[1]), "r"(a[2]), "r"(a[3]), "r"(b[0]), "r"(b[1]));
}
__device__ __forceinline__ unsigned cvt8x2(unsigned short v) {
    unsigned r;
    asm("cvt.rn.f16x2.e4m3x2 %0, %1;" : "=r"(r) : "h"(v));
    return r;
}
__device__ __forceinline__ float sigm(float x) { return 1.0f / (1.0f + __expf(-x)); }
__device__ __forceinline__ int growf(int n, int j0) { return ((n >> 5) << 10) + j0 + (n & 31); }

// ---------------- grid barrier ----------------
__device__ __forceinline__ void gridbar() {
    __syncthreads();
    if (threadIdx.x == 0) {
        __threadfence();
        unsigned gen = atomicAdd(&g_bar, 1u);
        unsigned target = gen - (gen % NBLK) + NBLK;
        while (*(volatile unsigned*)&g_bar < target) { }
        __threadfence();
    }
    __syncthreads();
}

// ---------------- decoder core ----------------
__device__ void dec_core(float* smf, int db, int tid,
                         const float* __restrict__ h2, const float* __restrict__ wdec,
                         const float* __restrict__ bdec, float* __restrict__ outp, int toff)
{
    float* sh2 = smf;
    float* sWd = smf + 32 * 260;
    const int o0 = db * 4;
    const int oo = tid & 3, b = (tid >> 2) & 31;
    float a0 = 0.0f, a1 = 0.0f, a2 = 0.0f, a3 = 0.0f;
    for (int k0 = 0; k0 < HID; k0 += 256) {
        __syncthreads();
        for (int li = tid; li < 2048; li += NTHR) {
            int r = li >> 6, c = li & 63;
            *(float4*)&sh2[r * 260 + c * 4] = *(const float4*)&h2[r * HID + k0 + c * 4];
        }
        for (int li = tid; li < 256; li += NTHR) {
            int r = li >> 6, c = li & 63;
            *(float4*)&sWd[r * 260 + c * 4] = *(const float4*)&wdec[(o0 + r) * HID + k0 + c * 4];
        }
        __syncthreads();
        if (tid < 128) {
#pragma unroll 16
            for (int k = 0; k < 256; k += 4) {
                a0 += sh2[b * 260 + k]     * sWd[oo * 260 + k];
                a1 += sh2[b * 260 + k + 1] * sWd[oo * 260 + k + 1];
                a2 += sh2[b * 260 + k + 2] * sWd[oo * 260 + k + 2];
                a3 += sh2[b * 260 + k + 3] * sWd[oo * 260 + k + 3];
            }
        }
    }
    if (tid < 128)
        outp[b * OUTW + toff + o0 + oo] = (a0 + a1) + (a2 + a3) + bdec[o0 + oo];
}

// ---------------- merged prep: tiling + Mw + bsM (one launch) ----------------
// blocks 0..2047: tiling/quantize; 2048..2559: Mw GEMM; 2560..2575: bsM
__global__ void k_prep(
    const float* __restrict__ wih1, const float* __restrict__ whh1,
    const float* __restrict__ wih2, const float* __restrict__ whh2,
    const float* __restrict__ wih3, const float* __restrict__ whh3,
    const float* __restrict__ seq,
    const float* __restrict__ bi1, const float* __restrict__ bh1,
    const float* __restrict__ bi2, const float* __restrict__ bh2,
    const float* __restrict__ bi3, const float* __restrict__ bh3,
    const float* __restrict__ wdec, const float* __restrict__ bdec)
{
    extern __shared__ __align__(16) char smraw[];
    const int tid = threadIdx.x, bid = blockIdx.x;

    if (bid >= 2560) {   // ---- bsM ----
        int r = (bid - 2560) * 256 + tid;
        float a = bi1[r] + bh1[r];
        for (int j = 0; j < IND; j++) a += wih1[r * IND + j] * bdec[j];
        g_bsM[r] = a;
        return;
    }
    if (bid >= 2048) {   // ---- Mw GEMM, tiled output ----
        const int mb = bid - 2048;
        float* sW1 = (float*)smraw;              // [128][133]
        float* sWd = (float*)smraw + 128 * 133;  // [132][64]
        const int r0 = (mb >> 4) * 128;
        const int c0 = (mb & 15) * 64;

        for (int li = tid; li < 128 * IND; li += 256) {
            int rr = li / IND, jj = li % IND;
            sW1[rr * 133 + jj] = wih1[(r0 + rr) * IND + jj];
        }
        for (int li = tid; li < IND * 64; li += 256) {
            int j = li >> 6, cc = li & 63;
            sWd[j * 64 + cc] = wdec[j * HID + c0 + cc];
        }
        __syncthreads();

        const int ty = tid >> 4, tx = tid & 15;
        float a[8][4];
#pragma unroll
        for (int i = 0; i < 8; i++)
#pragma unroll
            for (int q = 0; q < 4; q++) a[i][q] = 0.0f;

        for (int j = 0; j < IND; j++) {
            float4 wd = *(const float4*)&sWd[j * 64 + tx * 4];
#pragma unroll
            for (int i = 0; i < 8; i++) {
                float w1 = sW1[(ty + 16 * i) * 133 + j];
                a[i][0] += w1 * wd.x; a[i][1] += w1 * wd.y;
                a[i][2] += w1 * wd.z; a[i][3] += w1 * wd.w;
            }
        }
#pragma unroll
        for (int i = 0; i < 8; i++)
#pragma unroll
            for (int q = 0; q < 4; q++) {
                int r = r0 + ty + 16 * i, c = c0 + tx * 4 + q;
                float v = a[i][q];
                __half hi = __float2half_rn(v);
                int gate = r >> 10, win = r & 1023;
                int jbb = win >> 5, tr = gate * 32 + (win & 31);
                int kb = c >> 7, cc = c & 127;
                g_WT[5][jbb][kb][tr][cc] = hi;
                unsigned char* w8 = &g_W8T[5][jbb][kb][0][0];
                w8[tr * 144 + perm8(cc)] =
                    __nv_cvt_float_to_fp8((v - __half2float(hi)) * LO_SCALE,
                                          __NV_SATFINITE, __NV_E4M3);
            }
        return;
    }

    // ---- tiling part (blocks 0..2047) ----
    const long i0 = (long)bid * blockDim.x + tid;
    const long stride = 2048L * blockDim.x;

    for (long i = i0; i < 6L * 32 * 8 * 128 * 136; i += stride) {
        int cc = (int)(i % 136); long t1 = i / 136;
        int tr = (int)(t1 % 128); long t2 = t1 / 128;
        int kb = (int)(t2 % 8); long t3 = t2 / 8;
        int jbb = (int)(t3 % 32);
        int m = (int)(t3 / 32);
        if (cc >= 128) { g_WT[m][jbb][kb][tr][cc] = __float2half_rn(0.0f); continue; }
        if (m == 5) continue;
        const float* p = (m == 0) ? whh1 : (m == 1) ? wih2 : (m == 2) ? whh2
                                 : (m == 3) ? wih3 : whh3;
        int row = ((tr >> 5) << 10) + jbb * 32 + (tr & 31);
        int k = kb * 128 + cc;
        float v = p[(long)row * HID + k];
        __half hi = __float2half_rn(v);
        g_WT[m][jbb][kb][tr][cc] = hi;
        unsigned char* w8 = &g_W8T[m][jbb][kb][0][0];
        w8[tr * 144 + perm8(cc)] =
            __nv_cvt_float_to_fp8((v - __half2float(hi)) * LO_SCALE,
                                  __NV_SATFINITE, __NV_E4M3);
    }
    for (long i = i0; i < 6L * 32 * 8 * 128 * 16; i += stride) {
        int pb = (int)(i % 16); long t1 = i / 16;
        int tr = (int)(t1 % 128); long t2 = t1 / 128;
        int kb = (int)(t2 % 8); long t3 = t2 / 8;
        int jbb = (int)(t3 % 32); int m = (int)(t3 / 32);
        unsigned char* w8 = &g_W8T[m][jbb][kb][0][0];
        w8[tr * 144 + 128 + pb] = 0;
    }
    for (long i = i0; i < 32L * 2 * 128 * 136; i += stride) {
        int cc = (int)(i % 136); long t1 = i / 136;
        int tr = (int)(t1 % 128); long t2 = t1 / 128;
        int kb = (int)(t2 % 2); int jbb = (int)(t2 / 2);
        if (cc >= 128) { g_W1T[jbb][kb][tr][cc] = __float2half_rn(0.0f); continue; }
        int row = ((tr >> 5) << 10) + jbb * 32 + (tr & 31);
        int k = kb * 128 + cc;
        float v = (k < IND) ? wih1[(long)row * IND + k] : 0.0f;
        __half hi = __float2half_rn(v);
        g_W1T[jbb][kb][tr][cc] = hi;
        unsigned char* w8 = &g_W18T[jbb][kb][0][0];
        w8[tr * 144 + perm8(cc)] =
            __nv_cvt_float_to_fp8((v - __half2float(hi)) * LO_SCALE,
                                  __NV_SATFINITE, __NV_E4M3);
    }
    for (long i = i0; i < 32L * 2 * 128 * 16; i += stride) {
        int pb = (int)(i % 16); long t1 = i / 16;
        int tr = (int)(t1 % 128); long t2 = t1 / 128;
        int kb = (int)(t2 % 2); int jbb = (int)(t2 / 2);
        unsigned char* w8 = &g_W18T[jbb][kb][0][0];
        w8[tr * 144 + 128 + pb] = 0;
    }
    for (long i = i0; i < (long)NT * 2 * 32 * 136; i += stride) {
        int cc = (int)(i % 136); long t1 = i / 136;
        int b = (int)(t1 % 32); long t2 = t1 / 32;
        int kb = (int)(t2 % 2); int t = (int)(t2 / 2);
        float v = 0.0f;
        if (cc < 128) {
            int k = kb * 128 + cc;
            if (k < IND) v = seq[((long)b * NT + t) * IND + k];
        }
        g_xhT[t][kb][b][cc] = __float2half_rn(v);
    }
    for (long i = i0; i < 3L * G4; i += stride) {
        int l = (int)(i >> 12), r = (int)(i & 4095);
        const float* pi = (l == 0) ? bi1 : (l == 1) ? bi2 : bi3;
        const float* ph = (l == 0) ? bh1 : (l == 1) ? bh2 : bh3;
        g_bs[l][r] = pi[r] + ph[r];
    }
    for (long i = i0; i < 3L * NB * HID; i += stride) (&g_c[0][0][0])[i] = 0.0f;
    for (long i = i0; i < 2L * 3 * NB * HID; i += stride) (&g_hf[0][0][0][0])[i] = 0.0f;
    for (long i = i0; i < 2L * 3 * 8 * 32 * 136; i += stride)
        (&g_hhT[0][0][0][0][0])[i] = __float2half_rn(0.0f);
}

// ---------------- persistent kernel: all 100 steps ----------------
// gate blocks: warps 0..15 = MMA consumers (N=8 each), warp 16 = bulk-copy producer
__global__ void __launch_bounds__(NTHR, 1)
k_all(const float* __restrict__ wdec, const float* __restrict__ bdec,
      float* __restrict__ dout)
{
    extern __shared__ __align__(16) char smraw[];
    const int tid = threadIdx.x, bid = blockIdx.x;

    if (bid >= 96) {   // ---- decoder blocks ----
        const int db = bid - 96;
        for (int t = 0; t < NT; t++) {
            if (t > 0)
                dec_core((float*)smraw, db, tid, &g_hf[(t & 1) ^ 1][2][0][0],
                         wdec, bdec, dout, (t - 1) * IND);
            gridbar();
        }
        dec_core((float*)smraw, db, tid, &g_hf[1][2][0][0], wdec, bdec, dout, 99 * IND);
        return;
    }

    // ---- gate blocks ----
    const int l = bid >> 5, jb = bid & 31, j0 = jb << 5;
    const int lane = tid & 31, w = tid >> 5;     // w: 0..16
    const unsigned smb = sptr(smraw);
    const unsigned fullB = smb + CTRL;           // 3 x 8B
    const unsigned emptyB = smb + CTRL + 24;     // 3 x 8B
    float* G = (float*)(smraw + OF_G);           // [32][129] fp32 staging

    if (tid == 0) {
        for (int s = 0; s < DEPTH; s++) { mbar_init(fullB + s * 8, 1); mbar_init(emptyB + s * 8, 16); }
    }
    fence_async();
    __syncthreads();

    int sg = 0;
    for (int t = 0; t < NT; t++) {
        const int prev = (t & 1) ^ 1, cur = t & 1;
        const int gt = (t % 10) < 5;

        const char *Wt0, *Wt1, *W8t0, *W8t1, *At0, *At1;
        int nst1;
        if (l == 0) {
            if (gt) {
                Wt0 = (const char*)&g_W1T[jb][0][0][0];  W8t0 = (const char*)&g_W18T[jb][0][0][0];
                At0 = (const char*)&g_xhT[t][0][0][0];
                nst1 = 2;
            } else {
                Wt0 = (const char*)&g_WT[5][jb][0][0][0];
                W8t0 = (const char*)&g_W8T[5][jb][0][0][0];
                At0 = (const char*)&g_hhT[prev][2][0][0][0];
                nst1 = 8;
            }
            Wt1 = (const char*)&g_WT[0][jb][0][0][0]; W8t1 = (const char*)&g_W8T[0][jb][0][0][0];
            At1 = (const char*)&g_hhT[prev][0][0][0][0];
        } else if (l == 1) {
            Wt0 = (const char*)&g_WT[1][jb][0][0][0]; W8t0 = (const char*)&g_W8T[1][jb][0][0][0];
            At0 = (const char*)&g_hhT[prev][0][0][0][0];
            Wt1 = (const char*)&g_WT[2][jb][0][0][0]; W8t1 = (const char*)&g_W8T[2][jb][0][0][0];
            At1 = (const char*)&g_hhT[prev][1][0][0][0];
            nst1 = 8;
        } else {
            Wt0 = (const char*)&g_WT[3][jb][0][0][0]; W8t0 = (const char*)&g_W8T[3][jb][0][0][0];
            At0 = (const char*)&g_hhT[prev][1][0][0][0];
            Wt1 = (const char*)&g_WT[4][jb][0][0][0]; W8t1 = (const char*)&g_W8T[4][jb][0][0][0];
            At1 = (const char*)&g_hhT[prev][2][0][0][0];
            nst1 = 8;
        }
        const int nst = nst1 + 8;

        if (w == 16) {
            // ---- producer warp: bulk copies ----
            if (lane == 0) {
                for (int s = 0; s < nst; s++) {
                    const int g = sg + s;
                    const int slot = g % DEPTH, u = g / DEPTH;
                    if (u > 0) mbar_wait(emptyB + slot * 8, (u - 1) & 1);
                    const int seg = (s >= nst1);
                    const int kb = seg ? (s - nst1) : s;
                    const unsigned dst = smb + slot * SLOT;
                    const unsigned fb = fullB + slot * 8;
                    mbar_expect(fb, TXB);
                    bulkcp(dst, (seg ? Wt1 : Wt0) + (long)kb * TILE_WH, TILE_WH, fb);
                    bulkcp(dst + OF_W8, (seg ? W8t1 : W8t0) + (long)kb * TILE_W8, TILE_W8, fb);
                    bulkcp(dst + OF_AH, (seg ? At1 : At0) + (long)kb * TILE_A, TILE_A, fb);
                }
            }
        } else {
            // ---- consumer warps: MMA, N=8 per warp ----
            float accH[2][4], accL[2][4];
#pragma unroll
            for (int a = 0; a < 2; a++)
#pragma unroll
                for (int c = 0; c < 4; c++) { accH[a][c] = 0.0f; accL[a][c] = 0.0f; }

            for (int s = 0; s < nst; s++) {
                const int g = sg + s, slot = g % DEPTH;
                mbar_wait(fullB + slot * 8, (g / DEPTH) & 1);

                const char* sb = smraw + slot * SLOT;
                const __half* Abh = (const __half*)(sb + OF_AH);
                const __half* Bbh = (const __half*)sb;
                const unsigned char* Bb8 = (const unsigned char*)(sb + OF_W8);

#pragma unroll
                for (int kk = 0; kk < 128; kk += 16) {
                    unsigned ah0[4], ah1[4];
                    const int aoff = (lane & 15) * 136 + kk + ((lane >> 4) << 3);
                    ldmA4(ah0, sptr(Abh + aoff));
                    ldmA4(ah1, sptr(Abh + 16 * 136 + aoff));
                    unsigned bh[2], bl[2];
                    const int boff = ((w << 3) + (lane & 7)) * 136 +
                                     kk + (((lane >> 3) & 1) << 3);
                    ldmB2(bh, sptr(Bbh + boff));
                    unsigned u = *(const unsigned*)(Bb8 +
                                  ((w << 3) + (lane >> 2)) * 144 +
                                  kk + ((lane & 3) << 2));
                    bl[0] = cvt8x2((unsigned short)(u & 0xffffu));
                    bl[1] = cvt8x2((unsigned short)(u >> 16));
                    mma16816(accH[0], ah0, bh);
                    mma16816(accH[1], ah1, bh);
                    mma16816(accL[0], ah0, bl);
                    mma16816(accL[1], ah1, bl);
                }
                if (lane == 0) mbar_arrive(emptyB + slot * 8);
            }

            // stage gates + bias into dedicated G area
#pragma unroll
            for (int mi = 0; mi < 2; mi++)
#pragma unroll
                for (int r = 0; r < 4; r++) {
                    int m = mi * 16 + (lane >> 2) + ((r >> 1) << 3);
                    int n = (w << 3) + ((lane & 3) << 1) + (r & 1);
                    int row = growf(n, j0);
                    float bias = (l == 0 && !gt) ? g_bsM[row] : g_bs[l][row];
                    G[m * 129 + n] = accH[mi][r] + accL[mi][r] * LO_I + bias;
                }
        }
        __syncthreads();

        // ---- pointwise LSTM update (first 256 threads) ----
        if (tid < 256) {
            const int b = tid >> 3;
            const int jj0 = (tid & 7) << 2;
#pragma unroll
            for (int q = 0; q < 4; q++) {
                const int jj = jj0 + q, j = j0 + jj;
                float gi = G[b * 129 + jj];
                float gf = G[b * 129 + 32 + jj];
                float gg = G[b * 129 + 64 + jj];
                float go = G[b * 129 + 96 + jj];
                float c0 = g_c[l][b][j];
                float cn = sigm(gf) * c0 + sigm(gi) * tanhf(gg);
                float hn = sigm(go) * tanhf(cn);
                g_c[l][b][j] = cn;
                g_hf[cur][l][b][j] = hn;
                const int kb = j >> 7, cc = j & 127;
                g_hhT[cur][l][kb][b][cc] = __float2half_rn(hn);
            }
        }
        fence_async();
        sg += nst;
        gridbar();
    }
}

// ---------------- host ----------------
#define MW_SMEM 101888

extern "C" void kernel_launch(void* const* d_in, const int* in_sizes, int n_in,
                              void* d_out, int out_size) {
    (void)in_sizes; (void)n_in; (void)out_size;
    const float* seq  = (const float*)d_in[0];
    const float* Wih1 = (const float*)d_in[1];
    const float* Whh1 = (const float*)d_in[2];
    const float* bih1 = (const float*)d_in[3];
    const float* bhh1 = (const float*)d_in[4];
    const float* Wih2 = (const float*)d_in[5];
    const float* Whh2 = (const float*)d_in[6];
    const float* bih2 = (const float*)d_in[7];
    const float* bhh2 = (const float*)d_in[8];
    const float* Wih3 = (const float*)d_in[9];
    const float* Whh3 = (const float*)d_in[10];
    const float* bih3 = (const float*)d_in[11];
    const float* bhh3 = (const float*)d_in[12];
    const float* Wdec = (const float*)d_in[13];
    const float* bdec = (const float*)d_in[14];
    float* out = (float*)d_out;

    cudaFuncSetAttribute(k_all, cudaFuncAttributeMaxDynamicSharedMemorySize, SMEM_ALL);
    cudaFuncSetAttribute(k_prep, cudaFuncAttributeMaxDynamicSharedMemorySize, MW_SMEM);

    k_prep<<<2576, 256, MW_SMEM>>>(Wih1, Whh1, Wih2, Whh2, Wih3, Whh3, seq,
                                   bih1, bhh1, bih2, bhh2, bih3, bhh3, Wdec, bdec);
    k_all<<<NBLK, NTHR, SMEM_ALL>>>(Wdec, bdec, out);
}

// round 16
// speedup vs baseline: 3.9553x; 1.0791x over previous
#include <cuda_runtime.h>
#include <cuda_fp16.h>
#include <cuda_fp8.h>
#include <math.h>

#define HID   1024
#define G4    4096
#define NB    32
#define NT    100
#define IND   132
#define OUTW  13200
#define NBLK  129
#define NTHR  544
#define LO_SCALE 16384.0f
#define LO_I     (1.0f/16384.0f)

// K=128 stage tiles (bytes)
#define TILE_WH 34816   // 128 rows x 136 halves fp16
#define TILE_W8 18432   // 128 rows x 144 bytes fp8
#define TILE_A  8704    // 32 rows x 136 halves fp16
#define SLOT    61952
#define OF_W8   34816
#define OF_AH   53248
#define DEPTH   3
#define CTRL    185856  // 3*SLOT
#define OF_G    185920  // G staging: [2][32][132] fp32 = 33792 B
#define SMEM_ALL 219712
#define TXB     61952

// ---------------- persistent device scratch (pre-tiled, K=128 tiles) ----------------
// weight tiles: [matrix][jb][kb][row 128][136]  row = gate*32 + r, col = kb*128 + c
// matrices: 0 Whh1, 1 Wih2, 2 Whh2, 3 Wih3, 4 Whh3, 5 Mw(=Wih1@Wdec)
__device__ __half         g_WT[6][32][8][128][136];
__device__ unsigned char  g_W8T[6][32][8][128][144];  // fp8 e4m3 lo * 2^14, perm8 layout
__device__ __half         g_W1T[32][2][128][136];     // Wih1 padded to K=256
__device__ unsigned char  g_W18T[32][2][128][144];
__device__ __half         g_xhT[NT][2][32][136];      // frames, tiled
__device__ __half         g_hhT[2][3][8][32][136];    // h (fp16), tiled per kb
__device__ float          g_hf[2][3][NB][HID];        // fp32 h for decoder
__device__ float          g_c[3][NB][HID];
__device__ float          g_bs[3][G4];
__device__ float          g_bsM[G4];
__device__ unsigned       g_bar;

// perm within 16-byte group so a thread's fp8 fragment is one LDS.u32
__device__ __forceinline__ int perm8(int k) {
    int g = k >> 4, i = k & 15;
    return (g << 4) | (((i & 7) >> 1) << 2) | (((i >> 3) & 1) << 1) | (i & 1);
}

// ---------------- asm helpers ----------------
__device__ __forceinline__ unsigned sptr(const void* p) {
    return (unsigned)__cvta_generic_to_shared(p);
}
__device__ __forceinline__ void bulkcp(unsigned dst, const void* src, unsigned bytes,
                                       unsigned mbar) {
    asm volatile(
        "cp.async.bulk.shared::cluster.global.mbarrier::complete_tx::bytes "
        "[%0], [%1], %2, [%3];"
        :: "r"(dst), "l"(src), "r"(bytes), "r"(mbar) : "memory");
}
__device__ __forceinline__ void mbar_init(unsigned a, unsigned cnt) {
    asm volatile("mbarrier.init.shared.b64 [%0], %1;" :: "r"(a), "r"(cnt) : "memory");
}
__device__ __forceinline__ void mbar_expect(unsigned a, unsigned tx) {
    asm volatile("mbarrier.arrive.expect_tx.shared.b64 _, [%0], %1;"
                 :: "r"(a), "r"(tx) : "memory");
}
__device__ __forceinline__ void mbar_arrive(unsigned a) {
    asm volatile("mbarrier.arrive.shared.b64 _, [%0];" :: "r"(a) : "memory");
}
__device__ __forceinline__ void mbar_wait(unsigned a, unsigned par) {
    asm volatile(
        "{\n\t.reg .pred P;\n\t"
        "W_%=:\n\t"
        "mbarrier.try_wait.parity.acquire.cta.shared::cta.b64 P, [%0], %1, 0x989680;\n\t"
        "@P bra.uni D_%=;\n\t"
        "bra.uni W_%=;\n\t"
        "D_%=:\n\t}"
        :: "r"(a), "r"(par) : "memory");
}
__device__ __forceinline__ void fence_async() {
    asm volatile("fence.proxy.async.shared::cta;" ::: "memory");
}
__device__ __forceinline__ void ldmX4(unsigned a[4], unsigned addr) {
    asm volatile("ldmatrix.sync.aligned.m8n8.x4.shared.b16 {%0,%1,%2,%3}, [%4];"
                 : "=r"(a[0]), "=r"(a[1]), "=r"(a[2]), "=r"(a[3]) : "r"(addr));
}
__device__ __forceinline__ void mma16816(float c[4], const unsigned a[4], const unsigned b[2]) {
    asm volatile("mma.sync.aligned.m16n8k16.row.col.f32.f16.f16.f32 "
                 "{%0,%1,%2,%3}, {%4,%5,%6,%7}, {%8,%9}, {%0,%1,%2,%3};"
                 : "+f"(c[0]), "+f"(c[1]), "+f"(c[2]), "+f"(c[3])
                 : "r"(a[0]), "r"(a[1]), "r"(a[2]), "r"(a[3]), "r"(b[0]), "r"(b[1]));
}
__device__ __forceinline__ unsigned cvt8x2(unsigned short v) {
    unsigned r;
    asm("cvt.rn.f16x2.e4m3x2 %0, %1;" : "=r"(r) : "h"(v));
    return r;
}
__device__ __forceinline__ float sigm(float x) { return 1.0f / (1.0f + __expf(-x)); }
__device__ __forceinline__ int growf(int n, int j0) { return ((n >> 5) << 10) + j0 + (n & 31); }

// ---------------- grid barrier ----------------
__device__ __forceinline__ void gridbar() {
    __syncthreads();
    if (threadIdx.x == 0) {
        __threadfence();
        unsigned gen = atomicAdd(&g_bar, 1u);
        unsigned target = gen - (gen % NBLK) + NBLK;
        while (*(volatile unsigned*)&g_bar < target) { }
        __threadfence();
    }
    __syncthreads();
}

// ---------------- decoder core ----------------
__device__ void dec_core(float* smf, int db, int tid,
                         const float* __restrict__ h2, const float* __restrict__ wdec,
                         const float* __restrict__ bdec, float* __restrict__ outp, int toff)
{
    float* sh2 = smf;
    float* sWd = smf + 32 * 260;
    const int o0 = db * 4;
    const int oo = tid & 3, b = (tid >> 2) & 31;
    float a0 = 0.0f, a1 = 0.0f, a2 = 0.0f, a3 = 0.0f;
    for (int k0 = 0; k0 < HID; k0 += 256) {
        __syncthreads();
        for (int li = tid; li < 2048; li += NTHR) {
            int r = li >> 6, c = li & 63;
            *(float4*)&sh2[r * 260 + c * 4] = *(const float4*)&h2[r * HID + k0 + c * 4];
        }
        for (int li = tid; li < 256; li += NTHR) {
            int r = li >> 6, c = li & 63;
            *(float4*)&sWd[r * 260 + c * 4] = *(const float4*)&wdec[(o0 + r) * HID + k0 + c * 4];
        }
        __syncthreads();
        if (tid < 128) {
#pragma unroll 16
            for (int k = 0; k < 256; k += 4) {
                a0 += sh2[b * 260 + k]     * sWd[oo * 260 + k];
                a1 += sh2[b * 260 + k + 1] * sWd[oo * 260 + k + 1];
                a2 += sh2[b * 260 + k + 2] * sWd[oo * 260 + k + 2];
                a3 += sh2[b * 260 + k + 3] * sWd[oo * 260 + k + 3];
            }
        }
    }
    if (tid < 128)
        outp[b * OUTW + toff + o0 + oo] = (a0 + a1) + (a2 + a3) + bdec[o0 + oo];
}

// ---------------- merged prep: tiling + Mw + bsM (one launch) ----------------
__global__ void k_prep(
    const float* __restrict__ wih1, const float* __restrict__ whh1,
    const float* __restrict__ wih2, const float* __restrict__ whh2,
    const float* __restrict__ wih3, const float* __restrict__ whh3,
    const float* __restrict__ seq,
    const float* __restrict__ bi1, const float* __restrict__ bh1,
    const float* __restrict__ bi2, const float* __restrict__ bh2,
    const float* __restrict__ bi3, const float* __restrict__ bh3,
    const float* __restrict__ wdec, const float* __restrict__ bdec)
{
    extern __shared__ __align__(16) char smraw[];
    const int tid = threadIdx.x, bid = blockIdx.x;

    if (bid >= 2560) {   // ---- bsM ----
        int r = (bid - 2560) * 256 + tid;
        float a = bi1[r] + bh1[r];
        for (int j = 0; j < IND; j++) a += wih1[r * IND + j] * bdec[j];
        g_bsM[r] = a;
        return;
    }
    if (bid >= 2048) {   // ---- Mw GEMM, tiled output ----
        const int mb = bid - 2048;
        float* sW1 = (float*)smraw;              // [128][133]
        float* sWd = (float*)smraw + 128 * 133;  // [132][64]
        const int r0 = (mb >> 4) * 128;
        const int c0 = (mb & 15) * 64;

        for (int li = tid; li < 128 * IND; li += 256) {
            int rr = li / IND, jj = li % IND;
            sW1[rr * 133 + jj] = wih1[(r0 + rr) * IND + jj];
        }
        for (int li = tid; li < IND * 64; li += 256) {
            int j = li >> 6, cc = li & 63;
            sWd[j * 64 + cc] = wdec[j * HID + c0 + cc];
        }
        __syncthreads();

        const int ty = tid >> 4, tx = tid & 15;
        float a[8][4];
#pragma unroll
        for (int i = 0; i < 8; i++)
#pragma unroll
            for (int q = 0; q < 4; q++) a[i][q] = 0.0f;

        for (int j = 0; j < IND; j++) {
            float4 wd = *(const float4*)&sWd[j * 64 + tx * 4];
#pragma unroll
            for (int i = 0; i < 8; i++) {
                float w1 = sW1[(ty + 16 * i) * 133 + j];
                a[i][0] += w1 * wd.x; a[i][1] += w1 * wd.y;
                a[i][2] += w1 * wd.z; a[i][3] += w1 * wd.w;
            }
        }
#pragma unroll
        for (int i = 0; i < 8; i++)
#pragma unroll
            for (int q = 0; q < 4; q++) {
                int r = r0 + ty + 16 * i, c = c0 + tx * 4 + q;
                float v = a[i][q];
                __half hi = __float2half_rn(v);
                int gate = r >> 10, win = r & 1023;
                int jbb = win >> 5, tr = gate * 32 + (win & 31);
                int kb = c >> 7, cc = c & 127;
                g_WT[5][jbb][kb][tr][cc] = hi;
                unsigned char* w8 = &g_W8T[5][jbb][kb][0][0];
                w8[tr * 144 + perm8(cc)] =
                    __nv_cvt_float_to_fp8((v - __half2float(hi)) * LO_SCALE,
                                          __NV_SATFINITE, __NV_E4M3);
            }
        return;
    }

    // ---- tiling part (blocks 0..2047) ----
    const long i0 = (long)bid * blockDim.x + tid;
    const long stride = 2048L * blockDim.x;

    for (long i = i0; i < 6L * 32 * 8 * 128 * 136; i += stride) {
        int cc = (int)(i % 136); long t1 = i / 136;
        int tr = (int)(t1 % 128); long t2 = t1 / 128;
        int kb = (int)(t2 % 8); long t3 = t2 / 8;
        int jbb = (int)(t3 % 32);
        int m = (int)(t3 / 32);
        if (cc >= 128) { g_WT[m][jbb][kb][tr][cc] = __float2half_rn(0.0f); continue; }
        if (m == 5) continue;
        const float* p = (m == 0) ? whh1 : (m == 1) ? wih2 : (m == 2) ? whh2
                                 : (m == 3) ? wih3 : whh3;
        int row = ((tr >> 5) << 10) + jbb * 32 + (tr & 31);
        int k = kb * 128 + cc;
        float v = p[(long)row * HID + k];
        __half hi = __float2half_rn(v);
        g_WT[m][jbb][kb][tr][cc] = hi;
        unsigned char* w8 = &g_W8T[m][jbb][kb][0][0];
        w8[tr * 144 + perm8(cc)] =
            __nv_cvt_float_to_fp8((v - __half2float(hi)) * LO_SCALE,
                                  __NV_SATFINITE, __NV_E4M3);
    }
    for (long i = i0; i < 6L * 32 * 8 * 128 * 16; i += stride) {
        int pb = (int)(i % 16); long t1 = i / 16;
        int tr = (int)(t1 % 128); long t2 = t1 / 128;
        int kb = (int)(t2 % 8); long t3 = t2 / 8;
        int jbb = (int)(t3 % 32); int m = (int)(t3 / 32);
        unsigned char* w8 = &g_W8T[m][jbb][kb][0][0];
        w8[tr * 144 + 128 + pb] = 0;
    }
    for (long i = i0; i < 32L * 2 * 128 * 136; i += stride) {
        int cc = (int)(i % 136); long t1 = i / 136;
        int tr = (int)(t1 % 128); long t2 = t1 / 128;
        int kb = (int)(t2 % 2); int jbb = (int)(t2 / 2);
        if (cc >= 128) { g_W1T[jbb][kb][tr][cc] = __float2half_rn(0.0f); continue; }
        int row = ((tr >> 5) << 10) + jbb * 32 + (tr & 31);
        int k = kb * 128 + cc;
        float v = (k < IND) ? wih1[(long)row * IND + k] : 0.0f;
        __half hi = __float2half_rn(v);
        g_W1T[jbb][kb][tr][cc] = hi;
        unsigned char* w8 = &g_W18T[jbb][kb][0][0];
        w8[tr * 144 + perm8(cc)] =
            __nv_cvt_float_to_fp8((v - __half2float(hi)) * LO_SCALE,
                                  __NV_SATFINITE, __NV_E4M3);
    }
    for (long i = i0; i < 32L * 2 * 128 * 16; i += stride) {
        int pb = (int)(i % 16); long t1 = i / 16;
        int tr = (int)(t1 % 128); long t2 = t1 / 128;
        int kb = (int)(t2 % 2); int jbb = (int)(t2 / 2);
        unsigned char* w8 = &g_W18T[jbb][kb][0][0];
        w8[tr * 144 + 128 + pb] = 0;
    }
    for (long i = i0; i < (long)NT * 2 * 32 * 136; i += stride) {
        int cc = (int)(i % 136); long t1 = i / 136;
        int b = (int)(t1 % 32); long t2 = t1 / 32;
        int kb = (int)(t2 % 2); int t = (int)(t2 / 2);
        float v = 0.0f;
        if (cc < 128) {
            int k = kb * 128 + cc;
            if (k < IND) v = seq[((long)b * NT + t) * IND + k];
        }
        g_xhT[t][kb][b][cc] = __float2half_rn(v);
    }
    for (long i = i0; i < 3L * G4; i += stride) {
        int l = (int)(i >> 12), r = (int)(i & 4095);
        const float* pi = (l == 0) ? bi1 : (l == 1) ? bi2 : bi3;
        const float* ph = (l == 0) ? bh1 : (l == 1) ? bh2 : bh3;
        g_bs[l][r] = pi[r] + ph[r];
    }
    for (long i = i0; i < 3L * NB * HID; i += stride) (&g_c[0][0][0])[i] = 0.0f;
    for (long i = i0; i < 2L * 3 * NB * HID; i += stride) (&g_hf[0][0][0][0])[i] = 0.0f;
    for (long i = i0; i < 2L * 3 * 8 * 32 * 136; i += stride)
        (&g_hhT[0][0][0][0][0])[i] = __float2half_rn(0.0f);
}

// ---------------- persistent kernel: all 100 steps ----------------
// gate blocks: warps 0..15 = MMA consumers (8 N-warps x 2 K-groups), warp 16 = producer
__global__ void __launch_bounds__(NTHR, 1)
k_all(const float* __restrict__ wdec, const float* __restrict__ bdec,
      float* __restrict__ dout)
{
    extern __shared__ __align__(16) char smraw[];
    const int tid = threadIdx.x, bid = blockIdx.x;

    if (bid >= 96) {   // ---- decoder blocks ----
        const int db = bid - 96;
        for (int t = 0; t < NT; t++) {
            if (t > 0)
                dec_core((float*)smraw, db, tid, &g_hf[(t & 1) ^ 1][2][0][0],
                         wdec, bdec, dout, (t - 1) * IND);
            gridbar();
        }
        dec_core((float*)smraw, db, tid, &g_hf[1][2][0][0], wdec, bdec, dout, 99 * IND);
        return;
    }

    // ---- gate blocks ----
    const int l = bid >> 5, jb = bid & 31, j0 = jb << 5;
    const int lane = tid & 31, w = tid >> 5;     // w: 0..16
    const int grp = w >> 3, wn = w & 7;          // k-group, n-warp (N=16)
    const unsigned smb = sptr(smraw);
    const unsigned fullB = smb + CTRL;           // 3 x 8B
    const unsigned emptyB = smb + CTRL + 24;     // 3 x 8B
    float* G = (float*)(smraw + OF_G);           // [2][32][132] fp32 staging

    if (tid == 0) {
        for (int s = 0; s < DEPTH; s++) { mbar_init(fullB + s * 8, 1); mbar_init(emptyB + s * 8, 16); }
    }
    fence_async();
    __syncthreads();

    int sg = 0;
    for (int t = 0; t < NT; t++) {
        const int prev = (t & 1) ^ 1, cur = t & 1;
        const int gt = (t % 10) < 5;

        const char *Wt0, *Wt1, *W8t0, *W8t1, *At0, *At1;
        int nst1;
        if (l == 0) {
            if (gt) {
                Wt0 = (const char*)&g_W1T[jb][0][0][0];  W8t0 = (const char*)&g_W18T[jb][0][0][0];
                At0 = (const char*)&g_xhT[t][0][0][0];
                nst1 = 2;
            } else {
                Wt0 = (const char*)&g_WT[5][jb][0][0][0];
                W8t0 = (const char*)&g_W8T[5][jb][0][0][0];
                At0 = (const char*)&g_hhT[prev][2][0][0][0];
                nst1 = 8;
            }
            Wt1 = (const char*)&g_WT[0][jb][0][0][0]; W8t1 = (const char*)&g_W8T[0][jb][0][0][0];
            At1 = (const char*)&g_hhT[prev][0][0][0][0];
        } else if (l == 1) {
            Wt0 = (const char*)&g_WT[1][jb][0][0][0]; W8t0 = (const char*)&g_W8T[1][jb][0][0][0];
            At0 = (const char*)&g_hhT[prev][0][0][0][0];
            Wt1 = (const char*)&g_WT[2][jb][0][0][0]; W8t1 = (const char*)&g_W8T[2][jb][0][0][0];
            At1 = (const char*)&g_hhT[prev][1][0][0][0];
            nst1 = 8;
        } else {
            Wt0 = (const char*)&g_WT[3][jb][0][0][0]; W8t0 = (const char*)&g_W8T[3][jb][0][0][0];
            At0 = (const char*)&g_hhT[prev][1][0][0][0];
            Wt1 = (const char*)&g_WT[4][jb][0][0][0]; W8t1 = (const char*)&g_W8T[4][jb][0][0][0];
            At1 = (const char*)&g_hhT[prev][2][0][0][0];
            nst1 = 8;
        }
        const int nst = nst1 + 8;

        if (w == 16) {
            // ---- producer warp: bulk copies ----
            if (lane == 0) {
                for (int s = 0; s < nst; s++) {
                    const int g = sg + s;
                    const int slot = g % DEPTH, u = g / DEPTH;
                    if (u > 0) mbar_wait(emptyB + slot * 8, (u - 1) & 1);
                    const int seg = (s >= nst1);
                    const int kb = seg ? (s - nst1) : s;
                    const unsigned dst = smb + slot * SLOT;
                    const unsigned fb = fullB + slot * 8;
                    mbar_expect(fb, TXB);
                    bulkcp(dst, (seg ? Wt1 : Wt0) + (long)kb * TILE_WH, TILE_WH, fb);
                    bulkcp(dst + OF_W8, (seg ? W8t1 : W8t0) + (long)kb * TILE_W8, TILE_W8, fb);
                    bulkcp(dst + OF_AH, (seg ? At1 : At0) + (long)kb * TILE_A, TILE_A, fb);
                }
            }
        } else {
            // ---- consumer warps: N=16, half-K per warp ----
            float accH[2][2][4], accL[2][2][4];   // [mi][nf][r]
#pragma unroll
            for (int a = 0; a < 2; a++)
#pragma unroll
                for (int b = 0; b < 2; b++)
#pragma unroll
                    for (int c = 0; c < 4; c++) { accH[a][b][c] = 0.0f; accL[a][b][c] = 0.0f; }

            for (int s = 0; s < nst; s++) {
                const int g = sg + s, slot = g % DEPTH;
                mbar_wait(fullB + slot * 8, (g / DEPTH) & 1);

                const char* sb = smraw + slot * SLOT;
                const __half* Abh = (const __half*)(sb + OF_AH);
                const __half* Bbh = (const __half*)sb;
                const unsigned char* Bb8 = (const unsigned char*)(sb + OF_W8);

#pragma unroll
                for (int ki = 0; ki < 4; ki++) {
                    const int kk = (grp << 6) + (ki << 4);
                    unsigned ah0[4], ah1[4];
                    const int aoff = (lane & 15) * 136 + kk + ((lane >> 4) << 3);
                    ldmX4(ah0, sptr(Abh + aoff));
                    ldmX4(ah1, sptr(Abh + 16 * 136 + aoff));
                    // B: one x4 covers both n8 fragments
                    unsigned bh[4];
                    const int brow = (wn << 4) + ((lane >> 4) << 3) + (lane & 7);
                    const int bcol = kk + (((lane >> 3) & 1) << 3);
                    ldmX4(bh, sptr(Bbh + brow * 136 + bcol));
#pragma unroll
                    for (int nf = 0; nf < 2; nf++) {
                        unsigned bl[2];
                        unsigned u = *(const unsigned*)(Bb8 +
                                      ((wn << 4) + (nf << 3) + (lane >> 2)) * 144 +
                                      kk + ((lane & 3) << 2));
                        bl[0] = cvt8x2((unsigned short)(u & 0xffffu));
                        bl[1] = cvt8x2((unsigned short)(u >> 16));
                        mma16816(accH[0][nf], ah0, bh + nf * 2);
                        mma16816(accH[1][nf], ah1, bh + nf * 2);
                        mma16816(accL[0][nf], ah0, bl);
                        mma16816(accL[1][nf], ah1, bl);
                    }
                }
                if (lane == 0) mbar_arrive(emptyB + slot * 8);
            }

            // stage partial gates into this group's G plane (bias added by grp 0)
#pragma unroll
            for (int mi = 0; mi < 2; mi++)
#pragma unroll
                for (int nf = 0; nf < 2; nf++)
#pragma unroll
                    for (int r = 0; r < 4; r++) {
                        int m = mi * 16 + (lane >> 2) + ((r >> 1) << 3);
                        int n = (wn << 4) + (nf << 3) + ((lane & 3) << 1) + (r & 1);
                        float v = accH[mi][nf][r] + accL[mi][nf][r] * LO_I;
                        if (grp == 0) {
                            int row = growf(n, j0);
                            v += (l == 0 && !gt) ? g_bsM[row] : g_bs[l][row];
                        }
                        G[(grp * 32 + m) * 132 + n] = v;
                    }
        }
        __syncthreads();

        // ---- pointwise LSTM update (first 256 threads) ----
        if (tid < 256) {
            const int b = tid >> 3;
            const int jj0 = (tid & 7) << 2;
#pragma unroll
            for (int q = 0; q < 4; q++) {
                const int jj = jj0 + q, j = j0 + jj;
                float gi = G[b * 132 + jj]      + G[(32 + b) * 132 + jj];
                float gf = G[b * 132 + 32 + jj] + G[(32 + b) * 132 + 32 + jj];
                float gg = G[b * 132 + 64 + jj] + G[(32 + b) * 132 + 64 + jj];
                float go = G[b * 132 + 96 + jj] + G[(32 + b) * 132 + 96 + jj];
                float c0 = g_c[l][b][j];
                float cn = sigm(gf) * c0 + sigm(gi) * tanhf(gg);
                float hn = sigm(go) * tanhf(cn);
                g_c[l][b][j] = cn;
                g_hf[cur][l][b][j] = hn;
                const int kb = j >> 7, cc = j & 127;
                g_hhT[cur][l][kb][b][cc] = __float2half_rn(hn);
            }
        }
        fence_async();
        sg += nst;
        gridbar();
    }
}

// ---------------- host ----------------
#define MW_SMEM 101888

extern "C" void kernel_launch(void* const* d_in, const int* in_sizes, int n_in,
                              void* d_out, int out_size) {
    (void)in_sizes; (void)n_in; (void)out_size;
    const float* seq  = (const float*)d_in[0];
    const float* Wih1 = (const float*)d_in[1];
    const float* Whh1 = (const float*)d_in[2];
    const float* bih1 = (const float*)d_in[3];
    const float* bhh1 = (const float*)d_in[4];
    const float* Wih2 = (const float*)d_in[5];
    const float* Whh2 = (const float*)d_in[6];
    const float* bih2 = (const float*)d_in[7];
    const float* bhh2 = (const float*)d_in[8];
    const float* Wih3 = (const float*)d_in[9];
    const float* Whh3 = (const float*)d_in[10];
    const float* bih3 = (const float*)d_in[11];
    const float* bhh3 = (const float*)d_in[12];
    const float* Wdec = (const float*)d_in[13];
    const float* bdec = (const float*)d_in[14];
    float* out = (float*)d_out;

    cudaFuncSetAttribute(k_all, cudaFuncAttributeMaxDynamicSharedMemorySize, SMEM_ALL);
    cudaFuncSetAttribute(k_prep, cudaFuncAttributeMaxDynamicSharedMemorySize, MW_SMEM);

    k_prep<<<2576, 256, MW_SMEM>>>(Wih1, Whh1, Wih2, Whh2, Wih3, Whh3, seq,
                                   bih1, bhh1, bih2, bhh2, bih3, bhh3, Wdec, bdec);
    k_all<<<NBLK, NTHR, SMEM_ALL>>>(Wdec, bdec, out);
}